// round 3
// baseline (speedup 1.0000x reference)
#include <cuda_runtime.h>
#include <math.h>

#define NH     24
#define NKVH   8
#define HD     128
#define STXT   512
#define SIMG   4096
#define SALL   4608
#define DMODEL 3072

// ---------------- scratch (device globals: allocation-free) ----------------
__device__ float g_q[(size_t)NH * SALL * HD];     // [head][token][hd]
__device__ float g_k[(size_t)NKVH * SALL * HD];   // [kvhead][token][hd]
__device__ float g_v[(size_t)NKVH * SALL * HD];
__device__ float g_ao[(size_t)SALL * DMODEL];     // [token][h*HD+hd]

// ---------------- helpers ----------------
__device__ __forceinline__ unsigned f2tf(float x) {
    unsigned u;
    asm("cvt.rna.tf32.f32 %0, %1;" : "=r"(u) : "f"(x));
    return u;
}

// split fp32 into (hi, lo) tf32 pair packed in uint2; hi+lo recovers ~22 mantissa bits
__device__ __forceinline__ uint2 split2(float x) {
    uint2 r;
    r.x = f2tf(x);
    r.y = f2tf(x - __uint_as_float(r.x));
    return r;
}

__device__ __forceinline__ void mma8(float* c, const unsigned* a, const unsigned* b) {
    asm volatile(
        "mma.sync.aligned.m16n8k8.row.col.f32.tf32.tf32.f32 "
        "{%0,%1,%2,%3},{%4,%5,%6,%7},{%8,%9},{%0,%1,%2,%3};"
        : "+f"(c[0]), "+f"(c[1]), "+f"(c[2]), "+f"(c[3])
        : "r"(a[0]), "r"(a[1]), "r"(a[2]), "r"(a[3]), "r"(b[0]), "r"(b[1]));
}

// 3xTF32: c += a*b at near-fp32 precision
__device__ __forceinline__ void mma3x(float* c, const unsigned* ah, const unsigned* al,
                                      const unsigned* bh, const unsigned* bl) {
    mma8(c, al, bh);
    mma8(c, ah, bl);
    mma8(c, ah, bh);
}

// ---------------- 3xTF32 GEMM: C = A[M,K] * B[K,N] + bias ----------------
// MODE 0: C row-major [M,N]
// MODE 1: scatter to head-major scratch: dst[((n>>7)*SALL + tokoff + m)*HD + (n&127)]
template <int MODE>
__global__ __launch_bounds__(256, 1) void gemm_tf32(
    const float* __restrict__ A, const float* __restrict__ B,
    const float* __restrict__ bias, float* __restrict__ C,
    int M, int N, int K, int tokoff)
{
    extern __shared__ uint2 gsm[];
    uint2 (*As)[36]  = (uint2(*)[36])gsm;              // [m][k] hi/lo, 128x32
    uint2 (*Bs)[132] = (uint2(*)[132])(gsm + 128 * 36); // [k][n] hi/lo, 32x128

    const int tid  = threadIdx.x;
    const int bm   = blockIdx.y * 128;
    const int bn   = blockIdx.x * 128;
    const int warp = tid >> 5, lane = tid & 31;
    const int g    = lane >> 2, tg = lane & 3;
    const int wm   = (warp >> 2) * 64;
    const int wn   = (warp & 3) * 32;

    float acc[4][4][4];
#pragma unroll
    for (int i = 0; i < 4; i++)
#pragma unroll
        for (int j = 0; j < 4; j++)
#pragma unroll
            for (int r = 0; r < 4; r++) acc[i][j][r] = 0.f;

    const int ar = tid >> 3, ac4 = (tid & 7) * 4;     // A: 32 rows/pass x 8 float4-cols
    const int br = tid >> 5, bc4 = (tid & 31) * 4;    // B: 8 rows/pass x 32 float4-cols
    const float* Ag = A + (size_t)(bm + ar) * K + ac4;
    const float* Bg = B + (size_t)br * N + bn + bc4;
    const int KT = K >> 5;

    float4 ra[4], rb[4];
#pragma unroll
    for (int i = 0; i < 4; i++) ra[i] = *(const float4*)(Ag + (size_t)(32 * i) * K);
#pragma unroll
    for (int i = 0; i < 4; i++) rb[i] = *(const float4*)(Bg + (size_t)(8 * i) * N);

    for (int kt = 0; kt < KT; kt++) {
#pragma unroll
        for (int i = 0; i < 4; i++) {
            uint2 a0 = split2(ra[i].x), a1 = split2(ra[i].y);
            uint2 a2 = split2(ra[i].z), a3 = split2(ra[i].w);
            *(uint4*)&As[ar + 32 * i][ac4]     = make_uint4(a0.x, a0.y, a1.x, a1.y);
            *(uint4*)&As[ar + 32 * i][ac4 + 2] = make_uint4(a2.x, a2.y, a3.x, a3.y);
            uint2 b0 = split2(rb[i].x), b1 = split2(rb[i].y);
            uint2 b2 = split2(rb[i].z), b3 = split2(rb[i].w);
            *(uint4*)&Bs[br + 8 * i][bc4]     = make_uint4(b0.x, b0.y, b1.x, b1.y);
            *(uint4*)&Bs[br + 8 * i][bc4 + 2] = make_uint4(b2.x, b2.y, b3.x, b3.y);
        }
        __syncthreads();

        if (kt + 1 < KT) {
            const float* Ag2 = Ag + (kt + 1) * 32;
            const float* Bg2 = Bg + (size_t)(kt + 1) * 32 * N;
#pragma unroll
            for (int i = 0; i < 4; i++) ra[i] = *(const float4*)(Ag2 + (size_t)(32 * i) * K);
#pragma unroll
            for (int i = 0; i < 4; i++) rb[i] = *(const float4*)(Bg2 + (size_t)(8 * i) * N);
        }

#pragma unroll
        for (int kk = 0; kk < 4; kk++) {
            unsigned ah[4][4], al[4][4], bh[4][2], bl[4][2];
#pragma unroll
            for (int mt = 0; mt < 4; mt++) {
                int m0 = wm + mt * 16;
                uint2 q0 = As[m0 + g][kk * 8 + tg];
                uint2 q1 = As[m0 + g + 8][kk * 8 + tg];
                uint2 q2 = As[m0 + g][kk * 8 + tg + 4];
                uint2 q3 = As[m0 + g + 8][kk * 8 + tg + 4];
                ah[mt][0] = q0.x; ah[mt][1] = q1.x; ah[mt][2] = q2.x; ah[mt][3] = q3.x;
                al[mt][0] = q0.y; al[mt][1] = q1.y; al[mt][2] = q2.y; al[mt][3] = q3.y;
            }
#pragma unroll
            for (int nt = 0; nt < 4; nt++) {
                int n0 = wn + nt * 8;
                uint2 c0 = Bs[kk * 8 + tg][n0 + g];
                uint2 c1 = Bs[kk * 8 + tg + 4][n0 + g];
                bh[nt][0] = c0.x; bh[nt][1] = c1.x;
                bl[nt][0] = c0.y; bl[nt][1] = c1.y;
            }
#pragma unroll
            for (int mt = 0; mt < 4; mt++)
#pragma unroll
                for (int nt = 0; nt < 4; nt++)
                    mma3x(acc[mt][nt], ah[mt], al[mt], bh[nt], bl[nt]);
        }
        __syncthreads();
    }

    // epilogue
#pragma unroll
    for (int mt = 0; mt < 4; mt++) {
        int m = bm + wm + mt * 16 + g;
#pragma unroll
        for (int nt = 0; nt < 4; nt++) {
            int n = bn + wn + nt * 8 + tg * 2;
            float b0 = bias[n], b1 = bias[n + 1];
            float v00 = acc[mt][nt][0] + b0, v01 = acc[mt][nt][1] + b1;
            float v10 = acc[mt][nt][2] + b0, v11 = acc[mt][nt][3] + b1;
            if (MODE == 0) {
                C[(size_t)m * N + n]           = v00;
                C[(size_t)m * N + n + 1]       = v01;
                C[(size_t)(m + 8) * N + n]     = v10;
                C[(size_t)(m + 8) * N + n + 1] = v11;
            } else {
                int head = n >> 7, hd = n & 127;
                size_t b0i = ((size_t)head * SALL + tokoff + m) * HD + hd;
                size_t b1i = ((size_t)head * SALL + tokoff + m + 8) * HD + hd;
                C[b0i] = v00; C[b0i + 1] = v01;
                C[b1i] = v10; C[b1i + 1] = v11;
            }
        }
    }
}

// ---------------- RMSNorm + RoPE (in-place on q or k scratch) ----------------
__global__ __launch_bounds__(128) void norm_rope(
    float* __restrict__ x, const float* __restrict__ w,
    const float* __restrict__ aw, const float* __restrict__ rope)
{
    int row = blockIdx.x;            // head*SALL + token
    int token = row % SALL;
    int tid = threadIdx.x;

    float v = x[(size_t)row * HD + tid];
    float ss = v * v;
#pragma unroll
    for (int o = 16; o; o >>= 1) ss += __shfl_xor_sync(0xffffffffu, ss, o);
    __shared__ float red[4];
    if ((tid & 31) == 0) red[tid >> 5] = ss;
    __syncthreads();
    float tot = red[0] + red[1] + red[2] + red[3];
    float r = rsqrtf(tot * (1.0f / HD) + 1e-6f);
    float wt = (token < STXT) ? aw[tid] : w[tid];
    float xn = v * r * wt;

    float c = rope[(size_t)token * HD + tid];
    float s = rope[(size_t)(SALL + token) * HD + tid];
    float part = __shfl_xor_sync(0xffffffffu, xn, 1);
    float xr = (tid & 1) ? part : -part;
    x[(size_t)row * HD + tid] = xn * c + xr * s;
}

// ---------------- 3xTF32 flash attention: 128 q-rows/CTA, 32-key tiles ----------------
// smem (uint2 units): uQ[128][132] | union{ uK[32][132] / uP[128][36] } | uV[32][132]
__global__ __launch_bounds__(256, 1) void flash_attn()
{
    extern __shared__ uint2 fsm[];
    uint2 (*uQ)[132] = (uint2(*)[132])fsm;                       // 16896 uint2
    uint2* uni = (uint2*)(fsm + 128 * 132);
    uint2 (*uK)[132] = (uint2(*)[132])uni;                       // 4224
    uint2 (*uP)[36]  = (uint2(*)[36])uni;                        // 4608 (union)
    uint2 (*uV)[132] = (uint2(*)[132])(uni + 4608);              // 4224

    const int head = blockIdx.y;
    const int kvh  = head / (NH / NKVH);
    const int mb   = blockIdx.x * 128;
    const int tid  = threadIdx.x, warp = tid >> 5, lane = tid & 31;
    const int g    = lane >> 2, tg = lane & 3;
    const int m0   = warp * 16;
    const float scale = 0.08838834764831845f;  // 1/sqrt(128)

    // load Q tile (pre-scaled, hi/lo split)
    {
        const float* Qg = g_q + ((size_t)head * SALL + mb) * HD;
        int r = tid >> 1, c = (tid & 1) * 64;
#pragma unroll
        for (int i = 0; i < 16; i++) {
            float4 v = *(const float4*)(Qg + (size_t)r * HD + c + 4 * i);
            uint2 a0 = split2(v.x * scale), a1 = split2(v.y * scale);
            uint2 a2 = split2(v.z * scale), a3 = split2(v.w * scale);
            *(uint4*)&uQ[r][c + 4 * i]     = make_uint4(a0.x, a0.y, a1.x, a1.y);
            *(uint4*)&uQ[r][c + 4 * i + 2] = make_uint4(a2.x, a2.y, a3.x, a3.y);
        }
    }

    float o[16][4];
#pragma unroll
    for (int i = 0; i < 16; i++)
#pragma unroll
        for (int j = 0; j < 4; j++) o[i][j] = 0.f;
    float mprev0 = -INFINITY, mprev1 = -INFINITY, l0 = 0.f, l1 = 0.f;

    const int rldr = tid >> 3, cldr = (tid & 7) * 16;

    for (int jt = 0; jt < SALL / 32; jt++) {
        __syncthreads();  // Q visible (first iter) / prior PV reads of P,V done
        {
            const float* Kg = g_k + ((size_t)kvh * SALL + jt * 32 + rldr) * HD + cldr;
            const float* Vg = g_v + ((size_t)kvh * SALL + jt * 32 + rldr) * HD + cldr;
#pragma unroll
            for (int i = 0; i < 4; i++) {
                float4 kv = *(const float4*)(Kg + 4 * i);
                uint2 a0 = split2(kv.x), a1 = split2(kv.y);
                uint2 a2 = split2(kv.z), a3 = split2(kv.w);
                *(uint4*)&uK[rldr][cldr + 4 * i]     = make_uint4(a0.x, a0.y, a1.x, a1.y);
                *(uint4*)&uK[rldr][cldr + 4 * i + 2] = make_uint4(a2.x, a2.y, a3.x, a3.y);
                float4 vv = *(const float4*)(Vg + 4 * i);
                uint2 c0 = split2(vv.x), c1 = split2(vv.y);
                uint2 c2 = split2(vv.z), c3 = split2(vv.w);
                *(uint4*)&uV[rldr][cldr + 4 * i]     = make_uint4(c0.x, c0.y, c1.x, c1.y);
                *(uint4*)&uV[rldr][cldr + 4 * i + 2] = make_uint4(c2.x, c2.y, c3.x, c3.y);
            }
        }
        __syncthreads();

        // S = Q * K^T  (warp: 16 rows x 32 cols), 3xTF32
        float s[4][4];
#pragma unroll
        for (int nt = 0; nt < 4; nt++) { s[nt][0] = s[nt][1] = s[nt][2] = s[nt][3] = 0.f; }
#pragma unroll
        for (int kk = 0; kk < 16; kk++) {
            uint2 q0 = uQ[m0 + g][kk * 8 + tg];
            uint2 q1 = uQ[m0 + g + 8][kk * 8 + tg];
            uint2 q2 = uQ[m0 + g][kk * 8 + tg + 4];
            uint2 q3 = uQ[m0 + g + 8][kk * 8 + tg + 4];
            unsigned ah[4] = {q0.x, q1.x, q2.x, q3.x};
            unsigned al[4] = {q0.y, q1.y, q2.y, q3.y};
#pragma unroll
            for (int nt = 0; nt < 4; nt++) {
                uint2 k0 = uK[nt * 8 + g][kk * 8 + tg];
                uint2 k1 = uK[nt * 8 + g][kk * 8 + tg + 4];
                unsigned bh[2] = {k0.x, k1.x};
                unsigned bl[2] = {k0.y, k1.y};
                mma3x(s[nt], ah, al, bh, bl);
            }
        }

        // online softmax (rows g and g+8 of this warp's 16-row block)
        float mx0 = -INFINITY, mx1 = -INFINITY;
#pragma unroll
        for (int nt = 0; nt < 4; nt++) {
            mx0 = fmaxf(mx0, fmaxf(s[nt][0], s[nt][1]));
            mx1 = fmaxf(mx1, fmaxf(s[nt][2], s[nt][3]));
        }
        mx0 = fmaxf(mx0, __shfl_xor_sync(0xffffffffu, mx0, 1));
        mx0 = fmaxf(mx0, __shfl_xor_sync(0xffffffffu, mx0, 2));
        mx1 = fmaxf(mx1, __shfl_xor_sync(0xffffffffu, mx1, 1));
        mx1 = fmaxf(mx1, __shfl_xor_sync(0xffffffffu, mx1, 2));

        float mn0 = fmaxf(mprev0, mx0), mn1 = fmaxf(mprev1, mx1);
        float al0 = __expf(mprev0 - mn0), al1 = __expf(mprev1 - mn1);
        float p[4][4];
        float sum0 = 0.f, sum1 = 0.f;
#pragma unroll
        for (int nt = 0; nt < 4; nt++) {
            p[nt][0] = __expf(s[nt][0] - mn0);
            p[nt][1] = __expf(s[nt][1] - mn0);
            p[nt][2] = __expf(s[nt][2] - mn1);
            p[nt][3] = __expf(s[nt][3] - mn1);
            sum0 += p[nt][0] + p[nt][1];
            sum1 += p[nt][2] + p[nt][3];
        }
        sum0 += __shfl_xor_sync(0xffffffffu, sum0, 1);
        sum0 += __shfl_xor_sync(0xffffffffu, sum0, 2);
        sum1 += __shfl_xor_sync(0xffffffffu, sum1, 1);
        sum1 += __shfl_xor_sync(0xffffffffu, sum1, 2);
        l0 = l0 * al0 + sum0;
        l1 = l1 * al1 + sum1;
        mprev0 = mn0; mprev1 = mn1;
#pragma unroll
        for (int nt = 0; nt < 16; nt++) {
            o[nt][0] *= al0; o[nt][1] *= al0;
            o[nt][2] *= al1; o[nt][3] *= al1;
        }

        __syncthreads();  // all warps done reading uK before overwriting with uP

        // write P (hi/lo) into union region; own-warp rows only
#pragma unroll
        for (int nt = 0; nt < 4; nt++) {
            uint2 h00 = split2(p[nt][0]), h01 = split2(p[nt][1]);
            uint2 h10 = split2(p[nt][2]), h11 = split2(p[nt][3]);
            *(uint4*)&uP[m0 + g][nt * 8 + 2 * tg]     = make_uint4(h00.x, h00.y, h01.x, h01.y);
            *(uint4*)&uP[m0 + g + 8][nt * 8 + 2 * tg] = make_uint4(h10.x, h10.y, h11.x, h11.y);
        }
        __syncwarp();

        // O += P * V  (warp: 16 rows x 128 cols, K'=32), 3xTF32
#pragma unroll
        for (int kk = 0; kk < 4; kk++) {
            uint2 q0 = uP[m0 + g][kk * 8 + tg];
            uint2 q1 = uP[m0 + g + 8][kk * 8 + tg];
            uint2 q2 = uP[m0 + g][kk * 8 + tg + 4];
            uint2 q3 = uP[m0 + g + 8][kk * 8 + tg + 4];
            unsigned ah[4] = {q0.x, q1.x, q2.x, q3.x};
            unsigned al[4] = {q0.y, q1.y, q2.y, q3.y};
#pragma unroll
            for (int nt = 0; nt < 16; nt++) {
                uint2 v0 = uV[kk * 8 + tg][nt * 8 + g];
                uint2 v1 = uV[kk * 8 + 4 + tg][nt * 8 + g];
                unsigned bh[2] = {v0.x, v1.x};
                unsigned bl[2] = {v0.y, v1.y};
                mma3x(o[nt], ah, al, bh, bl);
            }
        }
    }

    // write out: g_ao[token][head*HD + col]
    float r0 = 1.f / l0, r1 = 1.f / l1;
    int tok0 = mb + m0 + g;
#pragma unroll
    for (int nt = 0; nt < 16; nt++) {
        int col = head * HD + nt * 8 + 2 * tg;
        float2 v0 = make_float2(o[nt][0] * r0, o[nt][1] * r0);
        float2 v1 = make_float2(o[nt][2] * r1, o[nt][3] * r1);
        *(float2*)&g_ao[(size_t)tok0 * DMODEL + col]       = v0;
        *(float2*)&g_ao[(size_t)(tok0 + 8) * DMODEL + col] = v1;
    }
}

// ---------------- launch ----------------
#define GEMM_SMEM  (128 * 36 * 8 + 32 * 132 * 8)                  // 70656
#define FLASH_SMEM ((128 * 132 + 4608 + 32 * 132) * 8)            // 205824

extern "C" void kernel_launch(void* const* d_in, const int* in_sizes, int n_in,
                              void* d_out, int out_size)
{
    const float* hs    = (const float*)d_in[0];
    const float* enc   = (const float*)d_in[1];
    const float* rope  = (const float*)d_in[2];
    const float* Wq    = (const float*)d_in[3];
    const float* bq    = (const float*)d_in[4];
    const float* Wk    = (const float*)d_in[5];
    const float* bk    = (const float*)d_in[6];
    const float* Wv    = (const float*)d_in[7];
    const float* bv    = (const float*)d_in[8];
    const float* aWq   = (const float*)d_in[9];
    const float* abq   = (const float*)d_in[10];
    const float* aWk   = (const float*)d_in[11];
    const float* abk   = (const float*)d_in[12];
    const float* aWv   = (const float*)d_in[13];
    const float* abv   = (const float*)d_in[14];
    const float* nq    = (const float*)d_in[15];
    const float* nk    = (const float*)d_in[16];
    const float* anq   = (const float*)d_in[17];
    const float* ank   = (const float*)d_in[18];
    const float* Wout  = (const float*)d_in[19];
    const float* bout  = (const float*)d_in[20];
    const float* Waout = (const float*)d_in[21];
    const float* baout = (const float*)d_in[22];
    float* out = (float*)d_out;

    float *pq, *pk, *pv, *pao;
    cudaGetSymbolAddress((void**)&pq, g_q);
    cudaGetSymbolAddress((void**)&pk, g_k);
    cudaGetSymbolAddress((void**)&pv, g_v);
    cudaGetSymbolAddress((void**)&pao, g_ao);

    cudaFuncSetAttribute(gemm_tf32<0>, cudaFuncAttributeMaxDynamicSharedMemorySize, GEMM_SMEM);
    cudaFuncSetAttribute(gemm_tf32<1>, cudaFuncAttributeMaxDynamicSharedMemorySize, GEMM_SMEM);
    cudaFuncSetAttribute(flash_attn,   cudaFuncAttributeMaxDynamicSharedMemorySize, FLASH_SMEM);

    // QKV projections (image stream -> tokens 512.., text stream -> tokens 0..511)
    gemm_tf32<1><<<dim3(24, 32), 256, GEMM_SMEM>>>(hs,  Wq,  bq,  pq, SIMG, NH * HD,   DMODEL, STXT);
    gemm_tf32<1><<<dim3(8,  32), 256, GEMM_SMEM>>>(hs,  Wk,  bk,  pk, SIMG, NKVH * HD, DMODEL, STXT);
    gemm_tf32<1><<<dim3(8,  32), 256, GEMM_SMEM>>>(hs,  Wv,  bv,  pv, SIMG, NKVH * HD, DMODEL, STXT);
    gemm_tf32<1><<<dim3(24, 4),  256, GEMM_SMEM>>>(enc, aWq, abq, pq, STXT, NH * HD,   DMODEL, 0);
    gemm_tf32<1><<<dim3(8,  4),  256, GEMM_SMEM>>>(enc, aWk, abk, pk, STXT, NKVH * HD, DMODEL, 0);
    gemm_tf32<1><<<dim3(8,  4),  256, GEMM_SMEM>>>(enc, aWv, abv, pv, STXT, NKVH * HD, DMODEL, 0);

    // RMSNorm + RoPE on q and k
    norm_rope<<<NH * SALL,   128>>>(pq, nq, anq, rope);
    norm_rope<<<NKVH * SALL, 128>>>(pk, nk, ank, rope);

    // attention
    flash_attn<<<dim3(SALL / 128, NH), 256, FLASH_SMEM>>>();

    // output projections: hid (image rows 512..4607) first, then enc (text rows 0..511)
    gemm_tf32<0><<<dim3(24, 32), 256, GEMM_SMEM>>>(pao + (size_t)STXT * DMODEL, Wout, bout,
                                                   out, SIMG, DMODEL, DMODEL, 0);
    gemm_tf32<0><<<dim3(24, 4), 256, GEMM_SMEM>>>(pao, Waout, baout,
                                                  out + (size_t)SIMG * DMODEL, STXT, DMODEL, DMODEL, 0);
}

// round 4
// speedup vs baseline: 1.0668x; 1.0668x over previous
#include <cuda_runtime.h>
#include <math.h>

#define NH     24
#define NKVH   8
#define HD     128
#define STXT   512
#define SIMG   4096
#define SALL   4608
#define DMODEL 3072

// ---------------- scratch (device globals: allocation-free) ----------------
__device__ float g_q[(size_t)NH * SALL * HD];     // [head][token][hd]
__device__ float g_k[(size_t)NKVH * SALL * HD];   // [kvhead][token][hd]
__device__ float g_v[(size_t)NKVH * SALL * HD];
__device__ float g_ao[(size_t)SALL * DMODEL];     // [token][h*HD+hd]

// ---------------- helpers ----------------
__device__ __forceinline__ unsigned f2tf(float x) {
    unsigned u;
    asm("cvt.rna.tf32.f32 %0, %1;" : "=r"(u) : "f"(x));
    return u;
}

// split fp32 into (hi, lo) tf32 pair packed in uint2
__device__ __forceinline__ uint2 split2(float x) {
    uint2 r;
    r.x = f2tf(x);
    r.y = f2tf(x - __uint_as_float(r.x));
    return r;
}

__device__ __forceinline__ void mma8(float* c, const unsigned* a, const unsigned* b) {
    asm volatile(
        "mma.sync.aligned.m16n8k8.row.col.f32.tf32.tf32.f32 "
        "{%0,%1,%2,%3},{%4,%5,%6,%7},{%8,%9},{%0,%1,%2,%3};"
        : "+f"(c[0]), "+f"(c[1]), "+f"(c[2]), "+f"(c[3])
        : "r"(a[0]), "r"(a[1]), "r"(a[2]), "r"(a[3]), "r"(b[0]), "r"(b[1]));
}

// 3xTF32: c += a*b at near-fp32 precision
__device__ __forceinline__ void mma3x(float* c, const unsigned* ah, const unsigned* al,
                                      const unsigned* bh, const unsigned* bl) {
    mma8(c, al, bh);
    mma8(c, ah, bl);
    mma8(c, ah, bh);
}

// ---------------- GEMM building blocks ----------------
__device__ __forceinline__ void gemm_store_tile(
    uint2 (*As)[36], uint2 (*Bs)[132],
    const float4* ra, const float4* rb, int ar, int ac4, int br, int bc4)
{
#pragma unroll
    for (int i = 0; i < 4; i++) {
        uint2 a0 = split2(ra[i].x), a1 = split2(ra[i].y);
        uint2 a2 = split2(ra[i].z), a3 = split2(ra[i].w);
        *(uint4*)&As[ar + 32 * i][ac4]     = make_uint4(a0.x, a0.y, a1.x, a1.y);
        *(uint4*)&As[ar + 32 * i][ac4 + 2] = make_uint4(a2.x, a2.y, a3.x, a3.y);
        uint2 b0 = split2(rb[i].x), b1 = split2(rb[i].y);
        uint2 b2 = split2(rb[i].z), b3 = split2(rb[i].w);
        *(uint4*)&Bs[br + 8 * i][bc4]     = make_uint4(b0.x, b0.y, b1.x, b1.y);
        *(uint4*)&Bs[br + 8 * i][bc4 + 2] = make_uint4(b2.x, b2.y, b3.x, b3.y);
    }
}

__device__ __forceinline__ void gemm_compute_tile(
    const uint2 (*As)[36], const uint2 (*Bs)[132],
    float acc[4][4][4], int wm, int wn, int g, int tg)
{
#pragma unroll
    for (int kk = 0; kk < 4; kk++) {
        unsigned ah[4][4], al[4][4], bh[4][2], bl[4][2];
#pragma unroll
        for (int mt = 0; mt < 4; mt++) {
            int m0 = wm + mt * 16;
            uint2 q0 = As[m0 + g][kk * 8 + tg];
            uint2 q1 = As[m0 + g + 8][kk * 8 + tg];
            uint2 q2 = As[m0 + g][kk * 8 + tg + 4];
            uint2 q3 = As[m0 + g + 8][kk * 8 + tg + 4];
            ah[mt][0] = q0.x; ah[mt][1] = q1.x; ah[mt][2] = q2.x; ah[mt][3] = q3.x;
            al[mt][0] = q0.y; al[mt][1] = q1.y; al[mt][2] = q2.y; al[mt][3] = q3.y;
        }
#pragma unroll
        for (int nt = 0; nt < 4; nt++) {
            int n0 = wn + nt * 8;
            uint2 c0 = Bs[kk * 8 + tg][n0 + g];
            uint2 c1 = Bs[kk * 8 + tg + 4][n0 + g];
            bh[nt][0] = c0.x; bh[nt][1] = c1.x;
            bl[nt][0] = c0.y; bl[nt][1] = c1.y;
        }
#pragma unroll
        for (int mt = 0; mt < 4; mt++)
#pragma unroll
            for (int nt = 0; nt < 4; nt++)
                mma3x(acc[mt][nt], ah[mt], al[mt], bh[nt], bl[nt]);
    }
}

// ---------------- 3xTF32 GEMM, double-buffered: C = A[M,K]*B[K,N] + bias ----------------
// MODE 0: C row-major [M,N]
// MODE 1: scatter to head-major scratch: dst[((n>>7)*SALL + tokoff + m)*HD + (n&127)]
#define GSTAGE 8832  // uint2 per stage: 128*36 + 32*132
template <int MODE>
__global__ __launch_bounds__(256, 1) void gemm_tf32(
    const float* __restrict__ A, const float* __restrict__ B,
    const float* __restrict__ bias, float* __restrict__ C,
    int M, int N, int K, int tokoff)
{
    extern __shared__ uint2 gsm[];
    uint2 (*As0)[36]  = (uint2(*)[36])gsm;
    uint2 (*Bs0)[132] = (uint2(*)[132])(gsm + 4608);
    uint2 (*As1)[36]  = (uint2(*)[36])(gsm + GSTAGE);
    uint2 (*Bs1)[132] = (uint2(*)[132])(gsm + GSTAGE + 4608);

    const int tid  = threadIdx.x;
    const int bm   = blockIdx.y * 128;
    const int bn   = blockIdx.x * 128;
    const int warp = tid >> 5, lane = tid & 31;
    const int g    = lane >> 2, tg = lane & 3;
    const int wm   = (warp >> 2) * 64;
    const int wn   = (warp & 3) * 32;

    float acc[4][4][4];
#pragma unroll
    for (int i = 0; i < 4; i++)
#pragma unroll
        for (int j = 0; j < 4; j++)
#pragma unroll
            for (int r = 0; r < 4; r++) acc[i][j][r] = 0.f;

    const int ar = tid >> 3, ac4 = (tid & 7) * 4;     // A: 32 rows/pass x 8 float4-cols
    const int br = tid >> 5, bc4 = (tid & 31) * 4;    // B: 8 rows/pass x 32 float4-cols
    const float* Ag = A + (size_t)(bm + ar) * K + ac4;
    const float* Bg = B + (size_t)br * N + bn + bc4;
    const int KT = K >> 5;

    float4 ra[4], rb[4];
    // prologue: tile 0 -> buf0, prefetch tile 1
#pragma unroll
    for (int i = 0; i < 4; i++) ra[i] = *(const float4*)(Ag + (size_t)(32 * i) * K);
#pragma unroll
    for (int i = 0; i < 4; i++) rb[i] = *(const float4*)(Bg + (size_t)(8 * i) * N);
    gemm_store_tile(As0, Bs0, ra, rb, ar, ac4, br, bc4);
    if (KT > 1) {
        const float* Ag2 = Ag + 32;
        const float* Bg2 = Bg + (size_t)32 * N;
#pragma unroll
        for (int i = 0; i < 4; i++) ra[i] = *(const float4*)(Ag2 + (size_t)(32 * i) * K);
#pragma unroll
        for (int i = 0; i < 4; i++) rb[i] = *(const float4*)(Bg2 + (size_t)(8 * i) * N);
    }
    __syncthreads();

    for (int kt = 0; kt < KT; kt++) {
        int cur = kt & 1;
        if (kt + 1 < KT)
            gemm_store_tile(cur ? As0 : As1, cur ? Bs0 : Bs1, ra, rb, ar, ac4, br, bc4);
        if (kt + 2 < KT) {
            const float* Ag2 = Ag + (kt + 2) * 32;
            const float* Bg2 = Bg + (size_t)(kt + 2) * 32 * N;
#pragma unroll
            for (int i = 0; i < 4; i++) ra[i] = *(const float4*)(Ag2 + (size_t)(32 * i) * K);
#pragma unroll
            for (int i = 0; i < 4; i++) rb[i] = *(const float4*)(Bg2 + (size_t)(8 * i) * N);
        }
        gemm_compute_tile(cur ? As1 : As0, cur ? Bs1 : Bs0, acc, wm, wn, g, tg);
        __syncthreads();
    }

    // epilogue
#pragma unroll
    for (int mt = 0; mt < 4; mt++) {
        int m = bm + wm + mt * 16 + g;
#pragma unroll
        for (int nt = 0; nt < 4; nt++) {
            int n = bn + wn + nt * 8 + tg * 2;
            float b0 = bias[n], b1 = bias[n + 1];
            float v00 = acc[mt][nt][0] + b0, v01 = acc[mt][nt][1] + b1;
            float v10 = acc[mt][nt][2] + b0, v11 = acc[mt][nt][3] + b1;
            if (MODE == 0) {
                C[(size_t)m * N + n]           = v00;
                C[(size_t)m * N + n + 1]       = v01;
                C[(size_t)(m + 8) * N + n]     = v10;
                C[(size_t)(m + 8) * N + n + 1] = v11;
            } else {
                int head = n >> 7, hd = n & 127;
                size_t b0i = ((size_t)head * SALL + tokoff + m) * HD + hd;
                size_t b1i = ((size_t)head * SALL + tokoff + m + 8) * HD + hd;
                C[b0i] = v00; C[b0i + 1] = v01;
                C[b1i] = v10; C[b1i + 1] = v11;
            }
        }
    }
}

// ---------------- RMSNorm + RoPE (in-place on q or k scratch) ----------------
__global__ __launch_bounds__(128) void norm_rope(
    float* __restrict__ x, const float* __restrict__ w,
    const float* __restrict__ aw, const float* __restrict__ rope)
{
    int row = blockIdx.x;            // head*SALL + token
    int token = row % SALL;
    int tid = threadIdx.x;

    float v = x[(size_t)row * HD + tid];
    float ss = v * v;
#pragma unroll
    for (int o = 16; o; o >>= 1) ss += __shfl_xor_sync(0xffffffffu, ss, o);
    __shared__ float red[4];
    if ((tid & 31) == 0) red[tid >> 5] = ss;
    __syncthreads();
    float tot = red[0] + red[1] + red[2] + red[3];
    float r = rsqrtf(tot * (1.0f / HD) + 1e-6f);
    float wt = (token < STXT) ? aw[tid] : w[tid];
    float xn = v * r * wt;

    float c = rope[(size_t)token * HD + tid];
    float s = rope[(size_t)(SALL + token) * HD + tid];
    float part = __shfl_xor_sync(0xffffffffu, xn, 1);
    float xr = (tid & 1) ? part : -part;
    x[(size_t)row * HD + tid] = xn * c + xr * s;
}

// ---------------- 3xTF32 flash attention: 128 q-rows/CTA, 32-key tiles ----------------
// smem (uint2): uQ[128][132] | uK[32][132] | uV[32][132]  (no P region; P via shuffles)
__global__ __launch_bounds__(256, 1) void flash_attn()
{
    extern __shared__ uint2 fsm[];
    uint2 (*uQ)[132] = (uint2(*)[132])fsm;                   // 16896 u2
    uint2 (*uK)[132] = (uint2(*)[132])(fsm + 16896);         // 4224
    uint2 (*uV)[132] = (uint2(*)[132])(fsm + 16896 + 4224);  // 4224

    const int head = blockIdx.y;
    const int kvh  = head / (NH / NKVH);
    const int mb   = blockIdx.x * 128;
    const int tid  = threadIdx.x, lane = tid & 31;
    const int g    = lane >> 2, tg = lane & 3;
    const int m0   = (tid >> 5) * 16;
    const float scale = 0.08838834764831845f;  // 1/sqrt(128)
    const int srcA = (lane & ~3) | (tg >> 1);        // shuffle src for P col tg
    const int srcB = (lane & ~3) | (2 + (tg >> 1));  // shuffle src for P col tg+4

    // load Q tile (pre-scaled, hi/lo split)
    {
        const float* Qg = g_q + ((size_t)head * SALL + mb) * HD;
        int r = tid >> 1, c = (tid & 1) * 64;
#pragma unroll
        for (int i = 0; i < 16; i++) {
            float4 v = *(const float4*)(Qg + (size_t)r * HD + c + 4 * i);
            uint2 a0 = split2(v.x * scale), a1 = split2(v.y * scale);
            uint2 a2 = split2(v.z * scale), a3 = split2(v.w * scale);
            *(uint4*)&uQ[r][c + 4 * i]     = make_uint4(a0.x, a0.y, a1.x, a1.y);
            *(uint4*)&uQ[r][c + 4 * i + 2] = make_uint4(a2.x, a2.y, a3.x, a3.y);
        }
    }

    float o[16][4];
#pragma unroll
    for (int i = 0; i < 16; i++)
#pragma unroll
        for (int j = 0; j < 4; j++) o[i][j] = 0.f;
    float mprev0 = -INFINITY, mprev1 = -INFINITY, l0 = 0.f, l1 = 0.f;

    const int rldr = tid >> 3, cldr = (tid & 7) * 16;
    const float* Kbase = g_k + ((size_t)kvh * SALL + rldr) * HD + cldr;
    const float* Vbase = g_v + ((size_t)kvh * SALL + rldr) * HD + cldr;

    float4 kr[4], vr[4];
#pragma unroll
    for (int i = 0; i < 4; i++) {
        kr[i] = *(const float4*)(Kbase + 4 * i);
        vr[i] = *(const float4*)(Vbase + 4 * i);
    }

    const int NT = SALL / 32;
    for (int jt = 0; jt < NT; jt++) {
        __syncthreads();  // prior QK/PV reads of uK/uV done (also covers initial Q store)
#pragma unroll
        for (int i = 0; i < 4; i++) {
            uint2 a0 = split2(kr[i].x), a1 = split2(kr[i].y);
            uint2 a2 = split2(kr[i].z), a3 = split2(kr[i].w);
            *(uint4*)&uK[rldr][cldr + 4 * i]     = make_uint4(a0.x, a0.y, a1.x, a1.y);
            *(uint4*)&uK[rldr][cldr + 4 * i + 2] = make_uint4(a2.x, a2.y, a3.x, a3.y);
            uint2 c0 = split2(vr[i].x), c1 = split2(vr[i].y);
            uint2 c2 = split2(vr[i].z), c3 = split2(vr[i].w);
            *(uint4*)&uV[rldr][cldr + 4 * i]     = make_uint4(c0.x, c0.y, c1.x, c1.y);
            *(uint4*)&uV[rldr][cldr + 4 * i + 2] = make_uint4(c2.x, c2.y, c3.x, c3.y);
        }
        __syncthreads();

        if (jt + 1 < NT) {  // prefetch next K/V tile; latency hidden behind compute
            const float* Kg = Kbase + (size_t)(jt + 1) * 32 * HD;
            const float* Vg = Vbase + (size_t)(jt + 1) * 32 * HD;
#pragma unroll
            for (int i = 0; i < 4; i++) {
                kr[i] = *(const float4*)(Kg + 4 * i);
                vr[i] = *(const float4*)(Vg + 4 * i);
            }
        }

        // S = Q * K^T  (warp: 16 rows x 32 cols), 3xTF32
        float s[4][4];
#pragma unroll
        for (int nt = 0; nt < 4; nt++) { s[nt][0] = s[nt][1] = s[nt][2] = s[nt][3] = 0.f; }
#pragma unroll
        for (int kk = 0; kk < 16; kk++) {
            uint2 q0 = uQ[m0 + g][kk * 8 + tg];
            uint2 q1 = uQ[m0 + g + 8][kk * 8 + tg];
            uint2 q2 = uQ[m0 + g][kk * 8 + tg + 4];
            uint2 q3 = uQ[m0 + g + 8][kk * 8 + tg + 4];
            unsigned ah[4] = {q0.x, q1.x, q2.x, q3.x};
            unsigned al[4] = {q0.y, q1.y, q2.y, q3.y};
#pragma unroll
            for (int nt = 0; nt < 4; nt++) {
                uint2 k0 = uK[nt * 8 + g][kk * 8 + tg];
                uint2 k1 = uK[nt * 8 + g][kk * 8 + tg + 4];
                unsigned bh[2] = {k0.x, k1.x};
                unsigned bl[2] = {k0.y, k1.y};
                mma3x(s[nt], ah, al, bh, bl);
            }
        }

        // online softmax (rows g and g+8 of this warp's 16-row block)
        float mx0 = -INFINITY, mx1 = -INFINITY;
#pragma unroll
        for (int nt = 0; nt < 4; nt++) {
            mx0 = fmaxf(mx0, fmaxf(s[nt][0], s[nt][1]));
            mx1 = fmaxf(mx1, fmaxf(s[nt][2], s[nt][3]));
        }
        mx0 = fmaxf(mx0, __shfl_xor_sync(0xffffffffu, mx0, 1));
        mx0 = fmaxf(mx0, __shfl_xor_sync(0xffffffffu, mx0, 2));
        mx1 = fmaxf(mx1, __shfl_xor_sync(0xffffffffu, mx1, 1));
        mx1 = fmaxf(mx1, __shfl_xor_sync(0xffffffffu, mx1, 2));

        float mn0 = fmaxf(mprev0, mx0), mn1 = fmaxf(mprev1, mx1);
        float al0 = __expf(mprev0 - mn0), al1 = __expf(mprev1 - mn1);
        float p[4][4];
        float sum0 = 0.f, sum1 = 0.f;
#pragma unroll
        for (int nt = 0; nt < 4; nt++) {
            p[nt][0] = __expf(s[nt][0] - mn0);
            p[nt][1] = __expf(s[nt][1] - mn0);
            p[nt][2] = __expf(s[nt][2] - mn1);
            p[nt][3] = __expf(s[nt][3] - mn1);
            sum0 += p[nt][0] + p[nt][1];
            sum1 += p[nt][2] + p[nt][3];
        }
        sum0 += __shfl_xor_sync(0xffffffffu, sum0, 1);
        sum0 += __shfl_xor_sync(0xffffffffu, sum0, 2);
        sum1 += __shfl_xor_sync(0xffffffffu, sum1, 1);
        sum1 += __shfl_xor_sync(0xffffffffu, sum1, 2);
        l0 = l0 * al0 + sum0;
        l1 = l1 * al1 + sum1;
        mprev0 = mn0; mprev1 = mn1;
#pragma unroll
        for (int nt = 0; nt < 16; nt++) {
            o[nt][0] *= al0; o[nt][1] *= al0;
            o[nt][2] *= al1; o[nt][3] *= al1;
        }

        // O += P * V  — P rearranged C-frag -> A-frag via register shuffles (no smem)
#pragma unroll
        for (int kk = 0; kk < 4; kk++) {
            float x0 = __shfl_sync(0xffffffffu, p[kk][0], srcA);
            float x1 = __shfl_sync(0xffffffffu, p[kk][1], srcA);
            float x2 = __shfl_sync(0xffffffffu, p[kk][2], srcA);
            float x3 = __shfl_sync(0xffffffffu, p[kk][3], srcA);
            float y0 = __shfl_sync(0xffffffffu, p[kk][0], srcB);
            float y1 = __shfl_sync(0xffffffffu, p[kk][1], srcB);
            float y2 = __shfl_sync(0xffffffffu, p[kk][2], srcB);
            float y3 = __shfl_sync(0xffffffffu, p[kk][3], srcB);
            bool odd = (tg & 1);
            float pa0 = odd ? x1 : x0;   // P[row g   ][kk*8 + tg]
            float pa1 = odd ? x3 : x2;   // P[row g+8 ][kk*8 + tg]
            float pa2 = odd ? y1 : y0;   // P[row g   ][kk*8 + tg+4]
            float pa3 = odd ? y3 : y2;   // P[row g+8 ][kk*8 + tg+4]
            uint2 u0 = split2(pa0), u1 = split2(pa1), u2 = split2(pa2), u3 = split2(pa3);
            unsigned ah[4] = {u0.x, u1.x, u2.x, u3.x};
            unsigned al2[4] = {u0.y, u1.y, u2.y, u3.y};
#pragma unroll
            for (int nt = 0; nt < 16; nt++) {
                uint2 v0 = uV[kk * 8 + tg][nt * 8 + g];
                uint2 v1 = uV[kk * 8 + 4 + tg][nt * 8 + g];
                unsigned bh[2] = {v0.x, v1.x};
                unsigned bl[2] = {v0.y, v1.y};
                mma3x(o[nt], ah, al2, bh, bl);
            }
        }
    }

    // write out: g_ao[token][head*HD + col]
    float r0 = 1.f / l0, r1 = 1.f / l1;
    int tok0 = mb + m0 + g;
#pragma unroll
    for (int nt = 0; nt < 16; nt++) {
        int col = head * HD + nt * 8 + 2 * tg;
        float2 v0 = make_float2(o[nt][0] * r0, o[nt][1] * r0);
        float2 v1 = make_float2(o[nt][2] * r1, o[nt][3] * r1);
        *(float2*)&g_ao[(size_t)tok0 * DMODEL + col]       = v0;
        *(float2*)&g_ao[(size_t)(tok0 + 8) * DMODEL + col] = v1;
    }
}

// ---------------- launch ----------------
#define GEMM_SMEM  (2 * GSTAGE * 8)                         // 141312
#define FLASH_SMEM ((16896 + 4224 + 4224) * 8)              // 202752

extern "C" void kernel_launch(void* const* d_in, const int* in_sizes, int n_in,
                              void* d_out, int out_size)
{
    const float* hs    = (const float*)d_in[0];
    const float* enc   = (const float*)d_in[1];
    const float* rope  = (const float*)d_in[2];
    const float* Wq    = (const float*)d_in[3];
    const float* bq    = (const float*)d_in[4];
    const float* Wk    = (const float*)d_in[5];
    const float* bk    = (const float*)d_in[6];
    const float* Wv    = (const float*)d_in[7];
    const float* bv    = (const float*)d_in[8];
    const float* aWq   = (const float*)d_in[9];
    const float* abq   = (const float*)d_in[10];
    const float* aWk   = (const float*)d_in[11];
    const float* abk   = (const float*)d_in[12];
    const float* aWv   = (const float*)d_in[13];
    const float* abv   = (const float*)d_in[14];
    const float* nq    = (const float*)d_in[15];
    const float* nk    = (const float*)d_in[16];
    const float* anq   = (const float*)d_in[17];
    const float* ank   = (const float*)d_in[18];
    const float* Wout  = (const float*)d_in[19];
    const float* bout  = (const float*)d_in[20];
    const float* Waout = (const float*)d_in[21];
    const float* baout = (const float*)d_in[22];
    float* out = (float*)d_out;

    float *pq, *pk, *pv, *pao;
    cudaGetSymbolAddress((void**)&pq, g_q);
    cudaGetSymbolAddress((void**)&pk, g_k);
    cudaGetSymbolAddress((void**)&pv, g_v);
    cudaGetSymbolAddress((void**)&pao, g_ao);

    cudaFuncSetAttribute(gemm_tf32<0>, cudaFuncAttributeMaxDynamicSharedMemorySize, GEMM_SMEM);
    cudaFuncSetAttribute(gemm_tf32<1>, cudaFuncAttributeMaxDynamicSharedMemorySize, GEMM_SMEM);
    cudaFuncSetAttribute(flash_attn,   cudaFuncAttributeMaxDynamicSharedMemorySize, FLASH_SMEM);

    // QKV projections (image stream -> tokens 512.., text stream -> tokens 0..511)
    gemm_tf32<1><<<dim3(24, 32), 256, GEMM_SMEM>>>(hs,  Wq,  bq,  pq, SIMG, NH * HD,   DMODEL, STXT);
    gemm_tf32<1><<<dim3(8,  32), 256, GEMM_SMEM>>>(hs,  Wk,  bk,  pk, SIMG, NKVH * HD, DMODEL, STXT);
    gemm_tf32<1><<<dim3(8,  32), 256, GEMM_SMEM>>>(hs,  Wv,  bv,  pv, SIMG, NKVH * HD, DMODEL, STXT);
    gemm_tf32<1><<<dim3(24, 4),  256, GEMM_SMEM>>>(enc, aWq, abq, pq, STXT, NH * HD,   DMODEL, 0);
    gemm_tf32<1><<<dim3(8,  4),  256, GEMM_SMEM>>>(enc, aWk, abk, pk, STXT, NKVH * HD, DMODEL, 0);
    gemm_tf32<1><<<dim3(8,  4),  256, GEMM_SMEM>>>(enc, aWv, abv, pv, STXT, NKVH * HD, DMODEL, 0);

    // RMSNorm + RoPE on q and k
    norm_rope<<<NH * SALL,   128>>>(pq, nq, anq, rope);
    norm_rope<<<NKVH * SALL, 128>>>(pk, nk, ank, rope);

    // attention
    flash_attn<<<dim3(SALL / 128, NH), 256, FLASH_SMEM>>>();

    // output projections: hid (image rows 512..4607) first, then enc (text rows 0..511)
    gemm_tf32<0><<<dim3(24, 32), 256, GEMM_SMEM>>>(pao + (size_t)STXT * DMODEL, Wout, bout,
                                                   out, SIMG, DMODEL, DMODEL, 0);
    gemm_tf32<0><<<dim3(24, 4), 256, GEMM_SMEM>>>(pao, Waout, baout,
                                                  out + (size_t)SIMG * DMODEL, STXT, DMODEL, DMODEL, 0);
}

// round 5
// speedup vs baseline: 2.4457x; 2.2927x over previous
#include <cuda_runtime.h>
#include <math.h>

#define NH     24
#define NKVH   8
#define HD     128
#define STXT   512
#define SIMG   4096
#define SALL   4608
#define DMODEL 3072

// ---------------- scratch (device globals: allocation-free) ----------------
__device__ float g_q[(size_t)NH * SALL * HD];     // [head][token][hd]
__device__ float g_k[(size_t)NKVH * SALL * HD];   // [kvhead][token][hd]
__device__ float g_v[(size_t)NKVH * SALL * HD];
__device__ float g_ao[(size_t)SALL * DMODEL];     // [token][h*HD+hd]

// ---------------- helpers ----------------
// pack two floats to bf16x2 (a in low half, b in high half)
__device__ __forceinline__ unsigned pk(float a, float b) {
    unsigned r;
    asm("cvt.rn.bf16x2.f32 %0, %1, %2;" : "=r"(r) : "f"(b), "f"(a));
    return r;
}

// hi/lo bf16 split of two floats: .x = hi pair, .y = lo (residual) pair
__device__ __forceinline__ uint2 packsplit(float a, float b) {
    uint2 r;
    r.x = pk(a, b);
    float ha = __uint_as_float(r.x << 16);
    float hb = __uint_as_float(r.x & 0xffff0000u);
    r.y = pk(a - ha, b - hb);
    return r;
}

__device__ __forceinline__ void mma16(float* c, const unsigned* a, const unsigned* b) {
    asm volatile(
        "mma.sync.aligned.m16n8k16.row.col.f32.bf16.bf16.f32 "
        "{%0,%1,%2,%3},{%4,%5,%6,%7},{%8,%9},{%0,%1,%2,%3};"
        : "+f"(c[0]), "+f"(c[1]), "+f"(c[2]), "+f"(c[3])
        : "r"(a[0]), "r"(a[1]), "r"(a[2]), "r"(a[3]), "r"(b[0]), "r"(b[1]));
}

// 3xBF16: c += a*b at ~16-mantissa-bit precision (drops lo*lo)
__device__ __forceinline__ void mma3b(float* c, const unsigned* ah, const unsigned* al,
                                      const unsigned* bh, const unsigned* bl) {
    mma16(c, al, bh);
    mma16(c, ah, bl);
    mma16(c, ah, bh);
}

// ---------------- GEMM: C = A[M,K]*B[K,N] + bias, 3xBF16, double-buffered ----------------
// smem (uint2): As[128][20] (kpair-major rows), Bs[16][132]
#define SA 20
#define SB 132
#define GSTAGE (128 * SA + 16 * SB)   // 4672 uint2 per stage

__device__ __forceinline__ void gemm_store_tile(
    uint2 (*As)[SA], uint2 (*Bs)[SB],
    const float4* ra, const float4* rb, int ar, int akp, int bkp, int bc4)
{
#pragma unroll
    for (int i = 0; i < 4; i++) {
        uint2 p0 = packsplit(ra[i].x, ra[i].y);
        uint2 p1 = packsplit(ra[i].z, ra[i].w);
        *(uint4*)&As[ar + 32 * i][akp] = make_uint4(p0.x, p0.y, p1.x, p1.y);
    }
    // rb[0]/rb[1]: rows 2*bkp, 2*bkp+1 ; rb[2]/rb[3]: rows 2*(bkp+8), 2*(bkp+8)+1
    {
        uint2 q0 = packsplit(rb[0].x, rb[1].x);
        uint2 q1 = packsplit(rb[0].y, rb[1].y);
        uint2 q2 = packsplit(rb[0].z, rb[1].z);
        uint2 q3 = packsplit(rb[0].w, rb[1].w);
        *(uint4*)&Bs[bkp][bc4]     = make_uint4(q0.x, q0.y, q1.x, q1.y);
        *(uint4*)&Bs[bkp][bc4 + 2] = make_uint4(q2.x, q2.y, q3.x, q3.y);
        uint2 r0 = packsplit(rb[2].x, rb[3].x);
        uint2 r1 = packsplit(rb[2].y, rb[3].y);
        uint2 r2 = packsplit(rb[2].z, rb[3].z);
        uint2 r3 = packsplit(rb[2].w, rb[3].w);
        *(uint4*)&Bs[bkp + 8][bc4]     = make_uint4(r0.x, r0.y, r1.x, r1.y);
        *(uint4*)&Bs[bkp + 8][bc4 + 2] = make_uint4(r2.x, r2.y, r3.x, r3.y);
    }
}

__device__ __forceinline__ void gemm_compute_tile(
    const uint2 (*As)[SA], const uint2 (*Bs)[SB],
    float acc[4][4][4], int wm, int wn, int g, int tg)
{
#pragma unroll
    for (int kk = 0; kk < 2; kk++) {
        unsigned ah[4][4], al[4][4], bh[4][2], bl[4][2];
#pragma unroll
        for (int mt = 0; mt < 4; mt++) {
            int m0 = wm + mt * 16;
            uint2 q0 = As[m0 + g][kk * 8 + tg];
            uint2 q1 = As[m0 + g + 8][kk * 8 + tg];
            uint2 q2 = As[m0 + g][kk * 8 + tg + 4];
            uint2 q3 = As[m0 + g + 8][kk * 8 + tg + 4];
            ah[mt][0] = q0.x; ah[mt][1] = q1.x; ah[mt][2] = q2.x; ah[mt][3] = q3.x;
            al[mt][0] = q0.y; al[mt][1] = q1.y; al[mt][2] = q2.y; al[mt][3] = q3.y;
        }
#pragma unroll
        for (int nt = 0; nt < 4; nt++) {
            int n0 = wn + nt * 8;
            uint2 c0 = Bs[kk * 8 + tg][n0 + g];
            uint2 c1 = Bs[kk * 8 + tg + 4][n0 + g];
            bh[nt][0] = c0.x; bh[nt][1] = c1.x;
            bl[nt][0] = c0.y; bl[nt][1] = c1.y;
        }
#pragma unroll
        for (int mt = 0; mt < 4; mt++)
#pragma unroll
            for (int nt = 0; nt < 4; nt++)
                mma3b(acc[mt][nt], ah[mt], al[mt], bh[nt], bl[nt]);
    }
}

// MODE 0: C row-major [M,N]
// MODE 1: scatter to head-major scratch: dst[((n>>7)*SALL + tokoff + m)*HD + (n&127)]
template <int MODE>
__global__ __launch_bounds__(256, 1) void gemm_bf16(
    const float* __restrict__ A, const float* __restrict__ B,
    const float* __restrict__ bias, float* __restrict__ C,
    int M, int N, int K, int tokoff)
{
    extern __shared__ uint2 gsm[];
    uint2 (*As0)[SA] = (uint2(*)[SA])gsm;
    uint2 (*Bs0)[SB] = (uint2(*)[SB])(gsm + 128 * SA);
    uint2 (*As1)[SA] = (uint2(*)[SA])(gsm + GSTAGE);
    uint2 (*Bs1)[SB] = (uint2(*)[SB])(gsm + GSTAGE + 128 * SA);

    const int tid  = threadIdx.x;
    const int bm   = blockIdx.y * 128;
    const int bn   = blockIdx.x * 128;
    const int warp = tid >> 5, lane = tid & 31;
    const int g    = lane >> 2, tg = lane & 3;
    const int wm   = (warp >> 2) * 64;
    const int wn   = (warp & 3) * 32;

    float acc[4][4][4];
#pragma unroll
    for (int i = 0; i < 4; i++)
#pragma unroll
        for (int j = 0; j < 4; j++)
#pragma unroll
            for (int r = 0; r < 4; r++) acc[i][j][r] = 0.f;

    const int ar  = tid >> 3, ac4 = (tid & 7) * 4;    // A: rows ar+32i, float cols ac4..ac4+3
    const int akp = ac4 >> 1;
    const int bkp = tid >> 5, bc4 = (tid & 31) * 4;   // B: kpairs bkp, bkp+8; cols bc4..bc4+3
    const float* Ag = A + (size_t)(bm + ar) * K + ac4;
    const float* Bg = B + (size_t)(2 * bkp) * N + bn + bc4;
    const int KT = K >> 5;

    float4 ra[4], rb[4];
#pragma unroll
    for (int i = 0; i < 4; i++) ra[i] = *(const float4*)(Ag + (size_t)(32 * i) * K);
    rb[0] = *(const float4*)(Bg);
    rb[1] = *(const float4*)(Bg + (size_t)N);
    rb[2] = *(const float4*)(Bg + (size_t)16 * N);
    rb[3] = *(const float4*)(Bg + (size_t)17 * N);
    gemm_store_tile(As0, Bs0, ra, rb, ar, akp, bkp, bc4);
    if (KT > 1) {
        const float* Ag2 = Ag + 32;
        const float* Bg2 = Bg + (size_t)32 * N;
#pragma unroll
        for (int i = 0; i < 4; i++) ra[i] = *(const float4*)(Ag2 + (size_t)(32 * i) * K);
        rb[0] = *(const float4*)(Bg2);
        rb[1] = *(const float4*)(Bg2 + (size_t)N);
        rb[2] = *(const float4*)(Bg2 + (size_t)16 * N);
        rb[3] = *(const float4*)(Bg2 + (size_t)17 * N);
    }
    __syncthreads();

    for (int kt = 0; kt < KT; kt++) {
        int cur = kt & 1;
        if (kt + 1 < KT)
            gemm_store_tile(cur ? As0 : As1, cur ? Bs0 : Bs1, ra, rb, ar, akp, bkp, bc4);
        if (kt + 2 < KT) {
            const float* Ag2 = Ag + (kt + 2) * 32;
            const float* Bg2 = Bg + (size_t)(kt + 2) * 32 * N;
#pragma unroll
            for (int i = 0; i < 4; i++) ra[i] = *(const float4*)(Ag2 + (size_t)(32 * i) * K);
            rb[0] = *(const float4*)(Bg2);
            rb[1] = *(const float4*)(Bg2 + (size_t)N);
            rb[2] = *(const float4*)(Bg2 + (size_t)16 * N);
            rb[3] = *(const float4*)(Bg2 + (size_t)17 * N);
        }
        gemm_compute_tile(cur ? As1 : As0, cur ? Bs1 : Bs0, acc, wm, wn, g, tg);
        __syncthreads();
    }

    // epilogue
#pragma unroll
    for (int mt = 0; mt < 4; mt++) {
        int m = bm + wm + mt * 16 + g;
#pragma unroll
        for (int nt = 0; nt < 4; nt++) {
            int n = bn + wn + nt * 8 + tg * 2;
            float b0 = bias[n], b1 = bias[n + 1];
            float v00 = acc[mt][nt][0] + b0, v01 = acc[mt][nt][1] + b1;
            float v10 = acc[mt][nt][2] + b0, v11 = acc[mt][nt][3] + b1;
            if (MODE == 0) {
                C[(size_t)m * N + n]           = v00;
                C[(size_t)m * N + n + 1]       = v01;
                C[(size_t)(m + 8) * N + n]     = v10;
                C[(size_t)(m + 8) * N + n + 1] = v11;
            } else {
                int head = n >> 7, hd = n & 127;
                size_t b0i = ((size_t)head * SALL + tokoff + m) * HD + hd;
                size_t b1i = ((size_t)head * SALL + tokoff + m + 8) * HD + hd;
                C[b0i] = v00; C[b0i + 1] = v01;
                C[b1i] = v10; C[b1i + 1] = v11;
            }
        }
    }
}

// ---------------- RMSNorm + RoPE (in-place on q or k scratch) ----------------
__global__ __launch_bounds__(128) void norm_rope(
    float* __restrict__ x, const float* __restrict__ w,
    const float* __restrict__ aw, const float* __restrict__ rope)
{
    int row = blockIdx.x;            // head*SALL + token
    int token = row % SALL;
    int tid = threadIdx.x;

    float v = x[(size_t)row * HD + tid];
    float ss = v * v;
#pragma unroll
    for (int o = 16; o; o >>= 1) ss += __shfl_xor_sync(0xffffffffu, ss, o);
    __shared__ float red[4];
    if ((tid & 31) == 0) red[tid >> 5] = ss;
    __syncthreads();
    float tot = red[0] + red[1] + red[2] + red[3];
    float r = rsqrtf(tot * (1.0f / HD) + 1e-6f);
    float wt = (token < STXT) ? aw[tid] : w[tid];
    float xn = v * r * wt;

    float c = rope[(size_t)token * HD + tid];
    float s = rope[(size_t)(SALL + token) * HD + tid];
    float part = __shfl_xor_sync(0xffffffffu, xn, 1);
    float xr = (tid & 1) ? part : -part;
    x[(size_t)row * HD + tid] = xn * c + xr * s;
}

// ---------------- 3xBF16 flash attention: 128 q-rows/CTA, 32-key tiles ----------------
// smem (uint2): uQ[128][68] (kpairs along hd) | uK[64][36] (kpair_hd x key) | uV[16][132] (kpair_key x hd)
#define SQ 68
#define SK 36
#define SV 132
__global__ __launch_bounds__(256, 1) void flash_attn()
{
    extern __shared__ uint2 fsm[];
    uint2 (*uQ)[SQ] = (uint2(*)[SQ])fsm;                          // 128*68 = 8704
    uint2 (*uK)[SK] = (uint2(*)[SK])(fsm + 128 * SQ);             // 64*36  = 2304
    uint2 (*uV)[SV] = (uint2(*)[SV])(fsm + 128 * SQ + 64 * SK);   // 16*132 = 2112

    const int head = blockIdx.y;
    const int kvh  = head / (NH / NKVH);
    const int mb   = blockIdx.x * 128;
    const int tid  = threadIdx.x, lane = tid & 31;
    const int g    = lane >> 2, tg = lane & 3;
    const int m0   = (tid >> 5) * 16;
    const float scale = 0.08838834764831845f;  // 1/sqrt(128)

    // load Q tile (pre-scaled, hi/lo bf16 split, kpairs along hd)
    {
        const float* Qg = g_q + ((size_t)head * SALL + mb) * HD;
        int r = tid >> 1, c0 = (tid & 1) * 64;
#pragma unroll
        for (int i = 0; i < 16; i++) {
            float4 v = *(const float4*)(Qg + (size_t)r * HD + c0 + 4 * i);
            uint2 p0 = packsplit(v.x * scale, v.y * scale);
            uint2 p1 = packsplit(v.z * scale, v.w * scale);
            *(uint4*)&uQ[r][(c0 >> 1) + 2 * i] = make_uint4(p0.x, p0.y, p1.x, p1.y);
        }
    }

    float o[16][4];
#pragma unroll
    for (int i = 0; i < 16; i++)
#pragma unroll
        for (int j = 0; j < 4; j++) o[i][j] = 0.f;
    float mprev0 = -INFINITY, mprev1 = -INFINITY, l0 = 0.f, l1 = 0.f;

    // K loader: thread -> key t = tid>>3, kpair cols c0+8i (pairs along hd)
    const int kt_ = tid >> 3, kc = tid & 7;
    // V loader: thread -> keypair kp = tid>>4, hd float2 col base cv (pairs along key)
    const int vkp = tid >> 4, cv = (tid & 15) * 2;

    const float* Kbase = g_k + ((size_t)kvh * SALL + kt_) * HD + 2 * kc;
    const float* V0base = g_v + ((size_t)kvh * SALL + 2 * vkp) * HD + cv;
    const float* V1base = V0base + HD;

    float2 kr[8], vr0[4], vr1[4];
#pragma unroll
    for (int i = 0; i < 8; i++) kr[i] = *(const float2*)(Kbase + 16 * i);
#pragma unroll
    for (int i = 0; i < 4; i++) {
        vr0[i] = *(const float2*)(V0base + 32 * i);
        vr1[i] = *(const float2*)(V1base + 32 * i);
    }

    const int NT = SALL / 32;
    for (int jt = 0; jt < NT; jt++) {
        __syncthreads();  // prior tile's reads of uK/uV done (covers initial Q store too)
#pragma unroll
        for (int i = 0; i < 8; i++)
            uK[kc + 8 * i][kt_] = packsplit(kr[i].x, kr[i].y);
#pragma unroll
        for (int i = 0; i < 4; i++) {
            uint2 a = packsplit(vr0[i].x, vr1[i].x);
            uint2 b = packsplit(vr0[i].y, vr1[i].y);
            *(uint4*)&uV[vkp][cv + 32 * i] = make_uint4(a.x, a.y, b.x, b.y);
        }
        __syncthreads();

        if (jt + 1 < NT) {  // prefetch next K/V tile
            const float* Kg = Kbase + (size_t)(jt + 1) * 32 * HD;
            const float* V0g = V0base + (size_t)(jt + 1) * 32 * HD;
            const float* V1g = V1base + (size_t)(jt + 1) * 32 * HD;
#pragma unroll
            for (int i = 0; i < 8; i++) kr[i] = *(const float2*)(Kg + 16 * i);
#pragma unroll
            for (int i = 0; i < 4; i++) {
                vr0[i] = *(const float2*)(V0g + 32 * i);
                vr1[i] = *(const float2*)(V1g + 32 * i);
            }
        }

        // S = Q * K^T  (warp: 16 rows x 32 keys), 3xBF16, k16 x 8 steps over HD
        float s[4][4];
#pragma unroll
        for (int nt = 0; nt < 4; nt++) { s[nt][0] = s[nt][1] = s[nt][2] = s[nt][3] = 0.f; }
#pragma unroll
        for (int kk = 0; kk < 8; kk++) {
            uint2 q0 = uQ[m0 + g][kk * 8 + tg];
            uint2 q1 = uQ[m0 + g + 8][kk * 8 + tg];
            uint2 q2 = uQ[m0 + g][kk * 8 + tg + 4];
            uint2 q3 = uQ[m0 + g + 8][kk * 8 + tg + 4];
            unsigned ah[4] = {q0.x, q1.x, q2.x, q3.x};
            unsigned al[4] = {q0.y, q1.y, q2.y, q3.y};
#pragma unroll
            for (int nt = 0; nt < 4; nt++) {
                uint2 k0 = uK[kk * 8 + tg][nt * 8 + g];
                uint2 k1 = uK[kk * 8 + tg + 4][nt * 8 + g];
                unsigned bh[2] = {k0.x, k1.x};
                unsigned bl[2] = {k0.y, k1.y};
                mma3b(s[nt], ah, al, bh, bl);
            }
        }

        // online softmax (rows g and g+8)
        float mx0 = -INFINITY, mx1 = -INFINITY;
#pragma unroll
        for (int nt = 0; nt < 4; nt++) {
            mx0 = fmaxf(mx0, fmaxf(s[nt][0], s[nt][1]));
            mx1 = fmaxf(mx1, fmaxf(s[nt][2], s[nt][3]));
        }
        mx0 = fmaxf(mx0, __shfl_xor_sync(0xffffffffu, mx0, 1));
        mx0 = fmaxf(mx0, __shfl_xor_sync(0xffffffffu, mx0, 2));
        mx1 = fmaxf(mx1, __shfl_xor_sync(0xffffffffu, mx1, 1));
        mx1 = fmaxf(mx1, __shfl_xor_sync(0xffffffffu, mx1, 2));

        float mn0 = fmaxf(mprev0, mx0), mn1 = fmaxf(mprev1, mx1);
        float al0 = __expf(mprev0 - mn0), al1 = __expf(mprev1 - mn1);
        float p[4][4];
        float sum0 = 0.f, sum1 = 0.f;
#pragma unroll
        for (int nt = 0; nt < 4; nt++) {
            p[nt][0] = __expf(s[nt][0] - mn0);
            p[nt][1] = __expf(s[nt][1] - mn0);
            p[nt][2] = __expf(s[nt][2] - mn1);
            p[nt][3] = __expf(s[nt][3] - mn1);
            sum0 += p[nt][0] + p[nt][1];
            sum1 += p[nt][2] + p[nt][3];
        }
        sum0 += __shfl_xor_sync(0xffffffffu, sum0, 1);
        sum0 += __shfl_xor_sync(0xffffffffu, sum0, 2);
        sum1 += __shfl_xor_sync(0xffffffffu, sum1, 1);
        sum1 += __shfl_xor_sync(0xffffffffu, sum1, 2);
        l0 = l0 * al0 + sum0;
        l1 = l1 * al1 + sum1;
        mprev0 = mn0; mprev1 = mn1;
#pragma unroll
        for (int nt = 0; nt < 16; nt++) {
            o[nt][0] *= al0; o[nt][1] *= al0;
            o[nt][2] *= al1; o[nt][3] *= al1;
        }

        // O += P * V : bf16 C-frag == A-frag layout -> no shuffles.
        // chunk kk covers keys 16kk..16kk+15 = S-tiles 2kk, 2kk+1
#pragma unroll
        for (int kk = 0; kk < 2; kk++) {
            uint2 u0 = packsplit(p[2 * kk][0],     p[2 * kk][1]);      // row g,   keys 2tg..+1
            uint2 u1 = packsplit(p[2 * kk][2],     p[2 * kk][3]);      // row g+8
            uint2 u2 = packsplit(p[2 * kk + 1][0], p[2 * kk + 1][1]);  // row g,   keys 2tg+8..+9
            uint2 u3 = packsplit(p[2 * kk + 1][2], p[2 * kk + 1][3]);  // row g+8
            unsigned ah[4] = {u0.x, u1.x, u2.x, u3.x};
            unsigned al2[4] = {u0.y, u1.y, u2.y, u3.y};
#pragma unroll
            for (int nt = 0; nt < 16; nt++) {
                uint2 v0 = uV[kk * 8 + tg][nt * 8 + g];
                uint2 v1 = uV[kk * 8 + tg + 4][nt * 8 + g];
                unsigned bh[2] = {v0.x, v1.x};
                unsigned bl[2] = {v0.y, v1.y};
                mma3b(o[nt], ah, al2, bh, bl);
            }
        }
    }

    // write out: g_ao[token][head*HD + col]
    float r0 = 1.f / l0, r1 = 1.f / l1;
    int tok0 = mb + m0 + g;
#pragma unroll
    for (int nt = 0; nt < 16; nt++) {
        int col = head * HD + nt * 8 + 2 * tg;
        float2 v0 = make_float2(o[nt][0] * r0, o[nt][1] * r0);
        float2 v1 = make_float2(o[nt][2] * r1, o[nt][3] * r1);
        *(float2*)&g_ao[(size_t)tok0 * DMODEL + col]       = v0;
        *(float2*)&g_ao[(size_t)(tok0 + 8) * DMODEL + col] = v1;
    }
}

// ---------------- launch ----------------
#define GEMM_SMEM  (2 * GSTAGE * 8)                               // 74752
#define FLASH_SMEM ((128 * SQ + 64 * SK + 16 * SV) * 8)           // 104960

extern "C" void kernel_launch(void* const* d_in, const int* in_sizes, int n_in,
                              void* d_out, int out_size)
{
    const float* hs    = (const float*)d_in[0];
    const float* enc   = (const float*)d_in[1];
    const float* rope  = (const float*)d_in[2];
    const float* Wq    = (const float*)d_in[3];
    const float* bq    = (const float*)d_in[4];
    const float* Wk    = (const float*)d_in[5];
    const float* bk    = (const float*)d_in[6];
    const float* Wv    = (const float*)d_in[7];
    const float* bv    = (const float*)d_in[8];
    const float* aWq   = (const float*)d_in[9];
    const float* abq   = (const float*)d_in[10];
    const float* aWk   = (const float*)d_in[11];
    const float* abk   = (const float*)d_in[12];
    const float* aWv   = (const float*)d_in[13];
    const float* abv   = (const float*)d_in[14];
    const float* nq    = (const float*)d_in[15];
    const float* nk    = (const float*)d_in[16];
    const float* anq   = (const float*)d_in[17];
    const float* ank   = (const float*)d_in[18];
    const float* Wout  = (const float*)d_in[19];
    const float* bout  = (const float*)d_in[20];
    const float* Waout = (const float*)d_in[21];
    const float* baout = (const float*)d_in[22];
    float* out = (float*)d_out;

    float *pq, *pk_, *pv, *pao;
    cudaGetSymbolAddress((void**)&pq, g_q);
    cudaGetSymbolAddress((void**)&pk_, g_k);
    cudaGetSymbolAddress((void**)&pv, g_v);
    cudaGetSymbolAddress((void**)&pao, g_ao);

    cudaFuncSetAttribute(gemm_bf16<0>, cudaFuncAttributeMaxDynamicSharedMemorySize, GEMM_SMEM);
    cudaFuncSetAttribute(gemm_bf16<1>, cudaFuncAttributeMaxDynamicSharedMemorySize, GEMM_SMEM);
    cudaFuncSetAttribute(flash_attn,   cudaFuncAttributeMaxDynamicSharedMemorySize, FLASH_SMEM);

    // QKV projections (image stream -> tokens 512.., text stream -> tokens 0..511)
    gemm_bf16<1><<<dim3(24, 32), 256, GEMM_SMEM>>>(hs,  Wq,  bq,  pq,  SIMG, NH * HD,   DMODEL, STXT);
    gemm_bf16<1><<<dim3(8,  32), 256, GEMM_SMEM>>>(hs,  Wk,  bk,  pk_, SIMG, NKVH * HD, DMODEL, STXT);
    gemm_bf16<1><<<dim3(8,  32), 256, GEMM_SMEM>>>(hs,  Wv,  bv,  pv,  SIMG, NKVH * HD, DMODEL, STXT);
    gemm_bf16<1><<<dim3(24, 4),  256, GEMM_SMEM>>>(enc, aWq, abq, pq,  STXT, NH * HD,   DMODEL, 0);
    gemm_bf16<1><<<dim3(8,  4),  256, GEMM_SMEM>>>(enc, aWk, abk, pk_, STXT, NKVH * HD, DMODEL, 0);
    gemm_bf16<1><<<dim3(8,  4),  256, GEMM_SMEM>>>(enc, aWv, abv, pv,  STXT, NKVH * HD, DMODEL, 0);

    // RMSNorm + RoPE on q and k
    norm_rope<<<NH * SALL,   128>>>(pq,  nq, anq, rope);
    norm_rope<<<NKVH * SALL, 128>>>(pk_, nk, ank, rope);

    // attention
    flash_attn<<<dim3(SALL / 128, NH), 256, FLASH_SMEM>>>();

    // output projections: hid (image rows 512..4607) first, then enc (text rows 0..511)
    gemm_bf16<0><<<dim3(24, 32), 256, GEMM_SMEM>>>(pao + (size_t)STXT * DMODEL, Wout, bout,
                                                   out, SIMG, DMODEL, DMODEL, 0);
    gemm_bf16<0><<<dim3(24, 4), 256, GEMM_SMEM>>>(pao, Waout, baout,
                                                  out + (size_t)SIMG * DMODEL, STXT, DMODEL, DMODEL, 0);
}

// round 6
// speedup vs baseline: 2.4601x; 1.0059x over previous
#include <cuda_runtime.h>
#include <math.h>

#define NH     24
#define NKVH   8
#define HD     128
#define STXT   512
#define SIMG   4096
#define SALL   4608
#define DMODEL 3072
#define NTILE  144          // SALL/32 key tiles

// ---------------- scratch (device globals: allocation-free) ----------------
__device__ float g_q[(size_t)NH * SALL * HD];     // [head][token][hd] (pre-norm)
__device__ float g_k[(size_t)NKVH * SALL * HD];
__device__ float g_v[(size_t)NKVH * SALL * HD];
__device__ float g_ao[(size_t)SALL * DMODEL];     // [token][h*HD+hd]
// packed bf16 hi/lo operand buffers for flash attention
__device__ uint2 g_qp[(size_t)NH * SALL * 64];            // [head][token][hdpair]
__device__ uint2 g_kp[(size_t)NKVH * NTILE * 64 * 32];    // [kvh][tile][hdpair][key]
__device__ uint2 g_vp[(size_t)NKVH * NTILE * 16 * 128];   // [kvh][tile][keypair][hd]

// ---------------- helpers ----------------
__device__ __forceinline__ unsigned pk(float a, float b) {
    unsigned r;
    asm("cvt.rn.bf16x2.f32 %0, %1, %2;" : "=r"(r) : "f"(b), "f"(a));
    return r;
}
// hi/lo bf16 split of two floats: .x = hi pair, .y = lo (residual) pair
__device__ __forceinline__ uint2 packsplit(float a, float b) {
    uint2 r;
    r.x = pk(a, b);
    float ha = __uint_as_float(r.x << 16);
    float hb = __uint_as_float(r.x & 0xffff0000u);
    r.y = pk(a - ha, b - hb);
    return r;
}

__device__ __forceinline__ void mma16(float* c, const unsigned* a, const unsigned* b) {
    asm volatile(
        "mma.sync.aligned.m16n8k16.row.col.f32.bf16.bf16.f32 "
        "{%0,%1,%2,%3},{%4,%5,%6,%7},{%8,%9},{%0,%1,%2,%3};"
        : "+f"(c[0]), "+f"(c[1]), "+f"(c[2]), "+f"(c[3])
        : "r"(a[0]), "r"(a[1]), "r"(a[2]), "r"(a[3]), "r"(b[0]), "r"(b[1]));
}
__device__ __forceinline__ void mma3b(float* c, const unsigned* ah, const unsigned* al,
                                      const unsigned* bh, const unsigned* bl) {
    mma16(c, al, bh);
    mma16(c, ah, bl);
    mma16(c, ah, bh);
}

__device__ __forceinline__ void cpasync16(unsigned dst, const void* src) {
    asm volatile("cp.async.cg.shared.global [%0], [%1], 16;" :: "r"(dst), "l"(src));
}

// ---------------- GEMM: C = A[M,K]*B[K,N] + bias, 3xBF16, double-buffered ----------------
#define SA 20
#define SB 132
#define GSTAGE (128 * SA + 16 * SB)   // 4672 uint2 per stage

__device__ __forceinline__ void gemm_store_tile(
    uint2 (*As)[SA], uint2 (*Bs)[SB],
    const float4* ra, const float4* rb, int ar, int akp, int bkp, int bc4)
{
#pragma unroll
    for (int i = 0; i < 4; i++) {
        uint2 p0 = packsplit(ra[i].x, ra[i].y);
        uint2 p1 = packsplit(ra[i].z, ra[i].w);
        *(uint4*)&As[ar + 32 * i][akp] = make_uint4(p0.x, p0.y, p1.x, p1.y);
    }
    {
        uint2 q0 = packsplit(rb[0].x, rb[1].x);
        uint2 q1 = packsplit(rb[0].y, rb[1].y);
        uint2 q2 = packsplit(rb[0].z, rb[1].z);
        uint2 q3 = packsplit(rb[0].w, rb[1].w);
        *(uint4*)&Bs[bkp][bc4]     = make_uint4(q0.x, q0.y, q1.x, q1.y);
        *(uint4*)&Bs[bkp][bc4 + 2] = make_uint4(q2.x, q2.y, q3.x, q3.y);
        uint2 r0 = packsplit(rb[2].x, rb[3].x);
        uint2 r1 = packsplit(rb[2].y, rb[3].y);
        uint2 r2 = packsplit(rb[2].z, rb[3].z);
        uint2 r3 = packsplit(rb[2].w, rb[3].w);
        *(uint4*)&Bs[bkp + 8][bc4]     = make_uint4(r0.x, r0.y, r1.x, r1.y);
        *(uint4*)&Bs[bkp + 8][bc4 + 2] = make_uint4(r2.x, r2.y, r3.x, r3.y);
    }
}

__device__ __forceinline__ void gemm_compute_tile(
    const uint2 (*As)[SA], const uint2 (*Bs)[SB],
    float acc[4][4][4], int wm, int wn, int g, int tg)
{
#pragma unroll
    for (int kk = 0; kk < 2; kk++) {
        unsigned ah[4][4], al[4][4], bh[4][2], bl[4][2];
#pragma unroll
        for (int mt = 0; mt < 4; mt++) {
            int m0 = wm + mt * 16;
            uint2 q0 = As[m0 + g][kk * 8 + tg];
            uint2 q1 = As[m0 + g + 8][kk * 8 + tg];
            uint2 q2 = As[m0 + g][kk * 8 + tg + 4];
            uint2 q3 = As[m0 + g + 8][kk * 8 + tg + 4];
            ah[mt][0] = q0.x; ah[mt][1] = q1.x; ah[mt][2] = q2.x; ah[mt][3] = q3.x;
            al[mt][0] = q0.y; al[mt][1] = q1.y; al[mt][2] = q2.y; al[mt][3] = q3.y;
        }
#pragma unroll
        for (int nt = 0; nt < 4; nt++) {
            int n0 = wn + nt * 8;
            uint2 c0 = Bs[kk * 8 + tg][n0 + g];
            uint2 c1 = Bs[kk * 8 + tg + 4][n0 + g];
            bh[nt][0] = c0.x; bh[nt][1] = c1.x;
            bl[nt][0] = c0.y; bl[nt][1] = c1.y;
        }
#pragma unroll
        for (int mt = 0; mt < 4; mt++)
#pragma unroll
            for (int nt = 0; nt < 4; nt++)
                mma3b(acc[mt][nt], ah[mt], al[mt], bh[nt], bl[nt]);
    }
}

template <int MODE>
__global__ __launch_bounds__(256, 1) void gemm_bf16(
    const float* __restrict__ A, const float* __restrict__ B,
    const float* __restrict__ bias, float* __restrict__ C,
    int M, int N, int K, int tokoff)
{
    extern __shared__ uint2 gsm[];
    uint2 (*As0)[SA] = (uint2(*)[SA])gsm;
    uint2 (*Bs0)[SB] = (uint2(*)[SB])(gsm + 128 * SA);
    uint2 (*As1)[SA] = (uint2(*)[SA])(gsm + GSTAGE);
    uint2 (*Bs1)[SB] = (uint2(*)[SB])(gsm + GSTAGE + 128 * SA);

    const int tid  = threadIdx.x;
    const int bm   = blockIdx.y * 128;
    const int bn   = blockIdx.x * 128;
    const int warp = tid >> 5, lane = tid & 31;
    const int g    = lane >> 2, tg = lane & 3;
    const int wm   = (warp >> 2) * 64;
    const int wn   = (warp & 3) * 32;

    float acc[4][4][4];
#pragma unroll
    for (int i = 0; i < 4; i++)
#pragma unroll
        for (int j = 0; j < 4; j++)
#pragma unroll
            for (int r = 0; r < 4; r++) acc[i][j][r] = 0.f;

    const int ar  = tid >> 3, ac4 = (tid & 7) * 4;
    const int akp = ac4 >> 1;
    const int bkp = tid >> 5, bc4 = (tid & 31) * 4;
    const float* Ag = A + (size_t)(bm + ar) * K + ac4;
    const float* Bg = B + (size_t)(2 * bkp) * N + bn + bc4;
    const int KT = K >> 5;

    float4 ra[4], rb[4];
#pragma unroll
    for (int i = 0; i < 4; i++) ra[i] = *(const float4*)(Ag + (size_t)(32 * i) * K);
    rb[0] = *(const float4*)(Bg);
    rb[1] = *(const float4*)(Bg + (size_t)N);
    rb[2] = *(const float4*)(Bg + (size_t)16 * N);
    rb[3] = *(const float4*)(Bg + (size_t)17 * N);
    gemm_store_tile(As0, Bs0, ra, rb, ar, akp, bkp, bc4);
    if (KT > 1) {
        const float* Ag2 = Ag + 32;
        const float* Bg2 = Bg + (size_t)32 * N;
#pragma unroll
        for (int i = 0; i < 4; i++) ra[i] = *(const float4*)(Ag2 + (size_t)(32 * i) * K);
        rb[0] = *(const float4*)(Bg2);
        rb[1] = *(const float4*)(Bg2 + (size_t)N);
        rb[2] = *(const float4*)(Bg2 + (size_t)16 * N);
        rb[3] = *(const float4*)(Bg2 + (size_t)17 * N);
    }
    __syncthreads();

    for (int kt = 0; kt < KT; kt++) {
        int cur = kt & 1;
        if (kt + 1 < KT)
            gemm_store_tile(cur ? As0 : As1, cur ? Bs0 : Bs1, ra, rb, ar, akp, bkp, bc4);
        if (kt + 2 < KT) {
            const float* Ag2 = Ag + (kt + 2) * 32;
            const float* Bg2 = Bg + (size_t)(kt + 2) * 32 * N;
#pragma unroll
            for (int i = 0; i < 4; i++) ra[i] = *(const float4*)(Ag2 + (size_t)(32 * i) * K);
            rb[0] = *(const float4*)(Bg2);
            rb[1] = *(const float4*)(Bg2 + (size_t)N);
            rb[2] = *(const float4*)(Bg2 + (size_t)16 * N);
            rb[3] = *(const float4*)(Bg2 + (size_t)17 * N);
        }
        gemm_compute_tile(cur ? As1 : As0, cur ? Bs1 : Bs0, acc, wm, wn, g, tg);
        __syncthreads();
    }

#pragma unroll
    for (int mt = 0; mt < 4; mt++) {
        int m = bm + wm + mt * 16 + g;
#pragma unroll
        for (int nt = 0; nt < 4; nt++) {
            int n = bn + wn + nt * 8 + tg * 2;
            float b0 = bias[n], b1 = bias[n + 1];
            float v00 = acc[mt][nt][0] + b0, v01 = acc[mt][nt][1] + b1;
            float v10 = acc[mt][nt][2] + b0, v11 = acc[mt][nt][3] + b1;
            if (MODE == 0) {
                C[(size_t)m * N + n]           = v00;
                C[(size_t)m * N + n + 1]       = v01;
                C[(size_t)(m + 8) * N + n]     = v10;
                C[(size_t)(m + 8) * N + n + 1] = v11;
            } else {
                int head = n >> 7, hd = n & 127;
                size_t b0i = ((size_t)head * SALL + tokoff + m) * HD + hd;
                size_t b1i = ((size_t)head * SALL + tokoff + m + 8) * HD + hd;
                C[b0i] = v00; C[b0i + 1] = v01;
                C[b1i] = v10; C[b1i + 1] = v11;
            }
        }
    }
}

// ---------------- RMSNorm + RoPE + pack ----------------
// QMODE 1: apply 1/sqrt(HD) scale, write g_qp[row][hdpair]
// QMODE 0: write g_kp[kvh][tile][hdpair][key] (transposed within 32-token tiles)
template <int QMODE>
__global__ __launch_bounds__(128) void norm_rope_pack(
    const float* __restrict__ x, const float* __restrict__ w,
    const float* __restrict__ aw, const float* __restrict__ rope)
{
    int row = blockIdx.x;            // head*SALL + token
    int token = row % SALL;
    int tid = threadIdx.x;

    float v = x[(size_t)row * HD + tid];
    float ss = v * v;
#pragma unroll
    for (int o = 16; o; o >>= 1) ss += __shfl_xor_sync(0xffffffffu, ss, o);
    __shared__ float red[4];
    if ((tid & 31) == 0) red[tid >> 5] = ss;
    __syncthreads();
    float tot = red[0] + red[1] + red[2] + red[3];
    float r = rsqrtf(tot * (1.0f / HD) + 1e-6f);
    float wt = (token < STXT) ? aw[tid] : w[tid];
    float xn = v * r * wt;

    float c = rope[(size_t)token * HD + tid];
    float s = rope[(size_t)(SALL + token) * HD + tid];
    float part = __shfl_xor_sync(0xffffffffu, xn, 1);
    float xr = (tid & 1) ? part : -part;
    float res = xn * c + xr * s;
    if (QMODE) res *= 0.08838834764831845f;   // 1/sqrt(128)

    float nb = __shfl_down_sync(0xffffffffu, res, 1);
    if ((tid & 1) == 0) {
        uint2 pkd = packsplit(res, nb);
        if (QMODE) {
            g_qp[(size_t)row * 64 + (tid >> 1)] = pkd;
        } else {
            int kvh = row / SALL;
            size_t idx = (((size_t)(kvh * NTILE + (token >> 5)) * 64) + (tid >> 1)) * 32
                         + (token & 31);
            g_kp[idx] = pkd;
        }
    }
}

// pack V: g_v float -> g_vp[kvh][tile][keypair][hd]
__global__ __launch_bounds__(128) void pack_v()
{
    int b = blockIdx.x;               // kvh*2304 + tile*16 + r
    int r = b & 15;
    int tile = (b >> 4) % NTILE;
    int kvh = b / (16 * NTILE);
    int hd = threadIdx.x;
    const float* v0 = g_v + ((size_t)kvh * SALL + tile * 32 + 2 * r) * HD + hd;
    float a = v0[0], c = v0[HD];
    g_vp[(((size_t)(kvh * NTILE + tile) * 16) + r) * 128 + hd] = packsplit(a, c);
}

// ---------------- 3xBF16 flash attention: 256 q-rows/CTA, 32-key tiles, cp.async ----------------
// smem (uint2): uQ[256][68] | K0[64][36] | K1 | V0[16][132] | V1
#define OFF_K0 17408
#define OFF_K1 19712
#define OFF_V0 22016
#define OFF_V1 24128
#define FLASH_U2 26240

__device__ __forceinline__ void issue_kv(unsigned sbase, int koff, int voff,
                                         int kvh, int jt, int tid)
{
    const uint2* ksrc = g_kp + (size_t)(kvh * NTILE + jt) * 64 * 32;
    const uint2* vsrc = g_vp + (size_t)(kvh * NTILE + jt) * 16 * 128;
#pragma unroll
    for (int c = tid; c < 1024; c += 512) {
        int kr = c >> 4, kc = (c & 15) * 2;
        cpasync16(sbase + (unsigned)(koff + kr * 36 + kc) * 8, ksrc + kr * 32 + kc);
        int vr = c >> 6, vc = (c & 63) * 2;
        cpasync16(sbase + (unsigned)(voff + vr * 132 + vc) * 8, vsrc + vr * 128 + vc);
    }
    asm volatile("cp.async.commit_group;");
}

__global__ __launch_bounds__(512, 1) void flash_attn()
{
    extern __shared__ uint2 fsm[];
    unsigned sbase = (unsigned)__cvta_generic_to_shared(fsm);

    const int head = blockIdx.y;
    const int kvh  = head / (NH / NKVH);
    const int mb   = blockIdx.x * 256;
    const int tid  = threadIdx.x, lane = tid & 31;
    const int g    = lane >> 2, tg = lane & 3;
    const int m0   = (tid >> 5) * 16;

    // load Q tile (pre-packed)
    {
        const uint2* Qg = g_qp + ((size_t)head * SALL + mb) * 64;
        int r = tid >> 1, b = (tid & 1) * 32;
#pragma unroll
        for (int i = 0; i < 16; i++) {
            uint4 v = *(const uint4*)(Qg + (size_t)r * 64 + b + 2 * i);
            *(uint4*)&fsm[r * 68 + b + 2 * i] = v;
        }
    }

    // prologue: tile 0 -> buf0
    issue_kv(sbase, OFF_K0, OFF_V0, kvh, 0, tid);

    float o[16][4];
#pragma unroll
    for (int i = 0; i < 16; i++)
#pragma unroll
        for (int j = 0; j < 4; j++) o[i][j] = 0.f;
    float mprev0 = -INFINITY, mprev1 = -INFINITY, l0 = 0.f, l1 = 0.f;

    for (int jt = 0; jt < NTILE; jt++) {
        int cur = jt & 1;
        if (jt + 1 < NTILE) {
            issue_kv(sbase, cur ? OFF_K0 : OFF_K1, cur ? OFF_V0 : OFF_V1, kvh, jt + 1, tid);
            asm volatile("cp.async.wait_group 1;");
        } else {
            asm volatile("cp.async.wait_group 0;");
        }
        __syncthreads();

        const uint2* Kb = fsm + (cur ? OFF_K1 : OFF_K0);
        const uint2* Vb = fsm + (cur ? OFF_V1 : OFF_V0);

        // S = Q * K^T  (warp: 16 rows x 32 keys)
        float s[4][4];
#pragma unroll
        for (int nt = 0; nt < 4; nt++) { s[nt][0] = s[nt][1] = s[nt][2] = s[nt][3] = 0.f; }
#pragma unroll
        for (int kk = 0; kk < 8; kk++) {
            uint2 q0 = fsm[(m0 + g) * 68 + kk * 8 + tg];
            uint2 q1 = fsm[(m0 + g + 8) * 68 + kk * 8 + tg];
            uint2 q2 = fsm[(m0 + g) * 68 + kk * 8 + tg + 4];
            uint2 q3 = fsm[(m0 + g + 8) * 68 + kk * 8 + tg + 4];
            unsigned ah[4] = {q0.x, q1.x, q2.x, q3.x};
            unsigned al[4] = {q0.y, q1.y, q2.y, q3.y};
#pragma unroll
            for (int nt = 0; nt < 4; nt++) {
                uint2 k0 = Kb[(kk * 8 + tg) * 36 + nt * 8 + g];
                uint2 k1 = Kb[(kk * 8 + tg + 4) * 36 + nt * 8 + g];
                unsigned bh[2] = {k0.x, k1.x};
                unsigned bl[2] = {k0.y, k1.y};
                mma3b(s[nt], ah, al, bh, bl);
            }
        }

        // online softmax (rows g and g+8)
        float mx0 = -INFINITY, mx1 = -INFINITY;
#pragma unroll
        for (int nt = 0; nt < 4; nt++) {
            mx0 = fmaxf(mx0, fmaxf(s[nt][0], s[nt][1]));
            mx1 = fmaxf(mx1, fmaxf(s[nt][2], s[nt][3]));
        }
        mx0 = fmaxf(mx0, __shfl_xor_sync(0xffffffffu, mx0, 1));
        mx0 = fmaxf(mx0, __shfl_xor_sync(0xffffffffu, mx0, 2));
        mx1 = fmaxf(mx1, __shfl_xor_sync(0xffffffffu, mx1, 1));
        mx1 = fmaxf(mx1, __shfl_xor_sync(0xffffffffu, mx1, 2));

        float mn0 = fmaxf(mprev0, mx0), mn1 = fmaxf(mprev1, mx1);
        float al0 = __expf(mprev0 - mn0), al1 = __expf(mprev1 - mn1);
        float p[4][4];
        float sum0 = 0.f, sum1 = 0.f;
#pragma unroll
        for (int nt = 0; nt < 4; nt++) {
            p[nt][0] = __expf(s[nt][0] - mn0);
            p[nt][1] = __expf(s[nt][1] - mn0);
            p[nt][2] = __expf(s[nt][2] - mn1);
            p[nt][3] = __expf(s[nt][3] - mn1);
            sum0 += p[nt][0] + p[nt][1];
            sum1 += p[nt][2] + p[nt][3];
        }
        sum0 += __shfl_xor_sync(0xffffffffu, sum0, 1);
        sum0 += __shfl_xor_sync(0xffffffffu, sum0, 2);
        sum1 += __shfl_xor_sync(0xffffffffu, sum1, 1);
        sum1 += __shfl_xor_sync(0xffffffffu, sum1, 2);
        l0 = l0 * al0 + sum0;
        l1 = l1 * al1 + sum1;
        mprev0 = mn0; mprev1 = mn1;
#pragma unroll
        for (int nt = 0; nt < 16; nt++) {
            o[nt][0] *= al0; o[nt][1] *= al0;
            o[nt][2] *= al1; o[nt][3] *= al1;
        }

        // O += P * V (C-frag == A-frag layout; no shuffles)
#pragma unroll
        for (int kk = 0; kk < 2; kk++) {
            uint2 u0 = packsplit(p[2 * kk][0],     p[2 * kk][1]);
            uint2 u1 = packsplit(p[2 * kk][2],     p[2 * kk][3]);
            uint2 u2 = packsplit(p[2 * kk + 1][0], p[2 * kk + 1][1]);
            uint2 u3 = packsplit(p[2 * kk + 1][2], p[2 * kk + 1][3]);
            unsigned ah[4] = {u0.x, u1.x, u2.x, u3.x};
            unsigned al2[4] = {u0.y, u1.y, u2.y, u3.y};
#pragma unroll
            for (int nt = 0; nt < 16; nt++) {
                uint2 v0 = Vb[(kk * 8 + tg) * 132 + nt * 8 + g];
                uint2 v1 = Vb[(kk * 8 + tg + 4) * 132 + nt * 8 + g];
                unsigned bh[2] = {v0.x, v1.x};
                unsigned bl[2] = {v0.y, v1.y};
                mma3b(o[nt], ah, al2, bh, bl);
            }
        }
        __syncthreads();  // done reading this buffer before next issue overwrites it
    }

    // write out: g_ao[token][head*HD + col]
    float r0 = 1.f / l0, r1 = 1.f / l1;
    int tok0 = mb + m0 + g;
#pragma unroll
    for (int nt = 0; nt < 16; nt++) {
        int col = head * HD + nt * 8 + 2 * tg;
        float2 v0 = make_float2(o[nt][0] * r0, o[nt][1] * r0);
        float2 v1 = make_float2(o[nt][2] * r1, o[nt][3] * r1);
        *(float2*)&g_ao[(size_t)tok0 * DMODEL + col]       = v0;
        *(float2*)&g_ao[(size_t)(tok0 + 8) * DMODEL + col] = v1;
    }
}

// ---------------- launch ----------------
#define GEMM_SMEM  (2 * GSTAGE * 8)        // 74752
#define FLASH_SMEM (FLASH_U2 * 8)          // 209920

extern "C" void kernel_launch(void* const* d_in, const int* in_sizes, int n_in,
                              void* d_out, int out_size)
{
    const float* hs    = (const float*)d_in[0];
    const float* enc   = (const float*)d_in[1];
    const float* rope  = (const float*)d_in[2];
    const float* Wq    = (const float*)d_in[3];
    const float* bq    = (const float*)d_in[4];
    const float* Wk    = (const float*)d_in[5];
    const float* bk    = (const float*)d_in[6];
    const float* Wv    = (const float*)d_in[7];
    const float* bv    = (const float*)d_in[8];
    const float* aWq   = (const float*)d_in[9];
    const float* abq   = (const float*)d_in[10];
    const float* aWk   = (const float*)d_in[11];
    const float* abk   = (const float*)d_in[12];
    const float* aWv   = (const float*)d_in[13];
    const float* abv   = (const float*)d_in[14];
    const float* nq    = (const float*)d_in[15];
    const float* nk    = (const float*)d_in[16];
    const float* anq   = (const float*)d_in[17];
    const float* ank   = (const float*)d_in[18];
    const float* Wout  = (const float*)d_in[19];
    const float* bout  = (const float*)d_in[20];
    const float* Waout = (const float*)d_in[21];
    const float* baout = (const float*)d_in[22];
    float* out = (float*)d_out;

    float *pq, *pk_, *pv, *pao;
    cudaGetSymbolAddress((void**)&pq, g_q);
    cudaGetSymbolAddress((void**)&pk_, g_k);
    cudaGetSymbolAddress((void**)&pv, g_v);
    cudaGetSymbolAddress((void**)&pao, g_ao);

    cudaFuncSetAttribute(gemm_bf16<0>, cudaFuncAttributeMaxDynamicSharedMemorySize, GEMM_SMEM);
    cudaFuncSetAttribute(gemm_bf16<1>, cudaFuncAttributeMaxDynamicSharedMemorySize, GEMM_SMEM);
    cudaFuncSetAttribute(flash_attn,   cudaFuncAttributeMaxDynamicSharedMemorySize, FLASH_SMEM);

    // QKV projections (image stream -> tokens 512.., text stream -> tokens 0..511)
    gemm_bf16<1><<<dim3(24, 32), 256, GEMM_SMEM>>>(hs,  Wq,  bq,  pq,  SIMG, NH * HD,   DMODEL, STXT);
    gemm_bf16<1><<<dim3(8,  32), 256, GEMM_SMEM>>>(hs,  Wk,  bk,  pk_, SIMG, NKVH * HD, DMODEL, STXT);
    gemm_bf16<1><<<dim3(8,  32), 256, GEMM_SMEM>>>(hs,  Wv,  bv,  pv,  SIMG, NKVH * HD, DMODEL, STXT);
    gemm_bf16<1><<<dim3(24, 4),  256, GEMM_SMEM>>>(enc, aWq, abq, pq,  STXT, NH * HD,   DMODEL, 0);
    gemm_bf16<1><<<dim3(8,  4),  256, GEMM_SMEM>>>(enc, aWk, abk, pk_, STXT, NKVH * HD, DMODEL, 0);
    gemm_bf16<1><<<dim3(8,  4),  256, GEMM_SMEM>>>(enc, aWv, abv, pv,  STXT, NKVH * HD, DMODEL, 0);

    // RMSNorm + RoPE + pack (q scaled), and V pack
    norm_rope_pack<1><<<NH * SALL,   128>>>(pq,  nq, anq, rope);
    norm_rope_pack<0><<<NKVH * SALL, 128>>>(pk_, nk, ank, rope);
    pack_v<<<NKVH * NTILE * 16, 128>>>();

    // attention
    flash_attn<<<dim3(SALL / 256, NH), 512, FLASH_SMEM>>>();

    // output projections: hid (image rows 512..4607) first, then enc (text rows 0..511)
    gemm_bf16<0><<<dim3(24, 32), 256, GEMM_SMEM>>>(pao + (size_t)STXT * DMODEL, Wout, bout,
                                                   out, SIMG, DMODEL, DMODEL, 0);
    gemm_bf16<0><<<dim3(24, 4), 256, GEMM_SMEM>>>(pao, Waout, baout,
                                                  out + (size_t)SIMG * DMODEL, STXT, DMODEL, DMODEL, 0);
}

// round 7
// speedup vs baseline: 2.4790x; 1.0077x over previous
#include <cuda_runtime.h>
#include <math.h>

#define NH     24
#define NKVH   8
#define HD     128
#define STXT   512
#define SIMG   4096
#define SALL   4608
#define DMODEL 3072
#define NT64   72           // SALL/64 key tiles

// ---------------- scratch (device globals: allocation-free) ----------------
__device__ float g_q[(size_t)NH * SALL * HD];     // [head][token][hd] (pre-norm)
__device__ float g_k[(size_t)NKVH * SALL * HD];
__device__ float g_v[(size_t)NKVH * SALL * HD];
__device__ float g_ao[(size_t)SALL * DMODEL];     // [token][h*HD+hd]
// packed bf16 hi/lo operand buffers for flash attention
__device__ uint2 g_qp[(size_t)NH * SALL * 64];            // [head][token][hdpair]
__device__ uint2 g_kp[(size_t)NKVH * NT64 * 64 * 64];     // [kvh][tile][hdpair][key64]
__device__ uint2 g_vp[(size_t)NKVH * NT64 * 32 * 128];    // [kvh][tile][keypair32][hd]

// ---------------- helpers ----------------
__device__ __forceinline__ unsigned pk(float a, float b) {
    unsigned r;
    asm("cvt.rn.bf16x2.f32 %0, %1, %2;" : "=r"(r) : "f"(b), "f"(a));
    return r;
}
// hi/lo bf16 split of two floats: .x = hi pair, .y = lo (residual) pair
__device__ __forceinline__ uint2 packsplit(float a, float b) {
    uint2 r;
    r.x = pk(a, b);
    float ha = __uint_as_float(r.x << 16);
    float hb = __uint_as_float(r.x & 0xffff0000u);
    r.y = pk(a - ha, b - hb);
    return r;
}

__device__ __forceinline__ void mma16(float* c, const unsigned* a, const unsigned* b) {
    asm volatile(
        "mma.sync.aligned.m16n8k16.row.col.f32.bf16.bf16.f32 "
        "{%0,%1,%2,%3},{%4,%5,%6,%7},{%8,%9},{%0,%1,%2,%3};"
        : "+f"(c[0]), "+f"(c[1]), "+f"(c[2]), "+f"(c[3])
        : "r"(a[0]), "r"(a[1]), "r"(a[2]), "r"(a[3]), "r"(b[0]), "r"(b[1]));
}
__device__ __forceinline__ void mma3b(float* c, const unsigned* ah, const unsigned* al,
                                      const unsigned* bh, const unsigned* bl) {
    mma16(c, al, bh);
    mma16(c, ah, bl);
    mma16(c, ah, bh);
}

__device__ __forceinline__ void cpasync16(unsigned dst, const void* src) {
    asm volatile("cp.async.cg.shared.global [%0], [%1], 16;" :: "r"(dst), "l"(src));
}

// ---------------- GEMM: C = A[M,K]*B[K,N] + bias, 3xBF16, double-buffered ----------------
#define SA 20
#define SB 132
#define GSTAGE (128 * SA + 16 * SB)   // 4672 uint2 per stage

__device__ __forceinline__ void gemm_store_tile(
    uint2 (*As)[SA], uint2 (*Bs)[SB],
    const float4* ra, const float4* rb, int ar, int akp, int bkp, int bc4)
{
#pragma unroll
    for (int i = 0; i < 4; i++) {
        uint2 p0 = packsplit(ra[i].x, ra[i].y);
        uint2 p1 = packsplit(ra[i].z, ra[i].w);
        *(uint4*)&As[ar + 32 * i][akp] = make_uint4(p0.x, p0.y, p1.x, p1.y);
    }
    {
        uint2 q0 = packsplit(rb[0].x, rb[1].x);
        uint2 q1 = packsplit(rb[0].y, rb[1].y);
        uint2 q2 = packsplit(rb[0].z, rb[1].z);
        uint2 q3 = packsplit(rb[0].w, rb[1].w);
        *(uint4*)&Bs[bkp][bc4]     = make_uint4(q0.x, q0.y, q1.x, q1.y);
        *(uint4*)&Bs[bkp][bc4 + 2] = make_uint4(q2.x, q2.y, q3.x, q3.y);
        uint2 r0 = packsplit(rb[2].x, rb[3].x);
        uint2 r1 = packsplit(rb[2].y, rb[3].y);
        uint2 r2 = packsplit(rb[2].z, rb[3].z);
        uint2 r3 = packsplit(rb[2].w, rb[3].w);
        *(uint4*)&Bs[bkp + 8][bc4]     = make_uint4(r0.x, r0.y, r1.x, r1.y);
        *(uint4*)&Bs[bkp + 8][bc4 + 2] = make_uint4(r2.x, r2.y, r3.x, r3.y);
    }
}

__device__ __forceinline__ void gemm_compute_tile(
    const uint2 (*As)[SA], const uint2 (*Bs)[SB],
    float acc[4][4][4], int wm, int wn, int g, int tg)
{
#pragma unroll
    for (int kk = 0; kk < 2; kk++) {
        unsigned ah[4][4], al[4][4], bh[4][2], bl[4][2];
#pragma unroll
        for (int mt = 0; mt < 4; mt++) {
            int m0 = wm + mt * 16;
            uint2 q0 = As[m0 + g][kk * 8 + tg];
            uint2 q1 = As[m0 + g + 8][kk * 8 + tg];
            uint2 q2 = As[m0 + g][kk * 8 + tg + 4];
            uint2 q3 = As[m0 + g + 8][kk * 8 + tg + 4];
            ah[mt][0] = q0.x; ah[mt][1] = q1.x; ah[mt][2] = q2.x; ah[mt][3] = q3.x;
            al[mt][0] = q0.y; al[mt][1] = q1.y; al[mt][2] = q2.y; al[mt][3] = q3.y;
        }
#pragma unroll
        for (int nt = 0; nt < 4; nt++) {
            int n0 = wn + nt * 8;
            uint2 c0 = Bs[kk * 8 + tg][n0 + g];
            uint2 c1 = Bs[kk * 8 + tg + 4][n0 + g];
            bh[nt][0] = c0.x; bh[nt][1] = c1.x;
            bl[nt][0] = c0.y; bl[nt][1] = c1.y;
        }
#pragma unroll
        for (int mt = 0; mt < 4; mt++)
#pragma unroll
            for (int nt = 0; nt < 4; nt++)
                mma3b(acc[mt][nt], ah[mt], al[mt], bh[nt], bl[nt]);
    }
}

template <int MODE>
__global__ __launch_bounds__(256, 1) void gemm_bf16(
    const float* __restrict__ A, const float* __restrict__ B,
    const float* __restrict__ bias, float* __restrict__ C,
    int M, int N, int K, int tokoff)
{
    extern __shared__ uint2 gsm[];
    uint2 (*As0)[SA] = (uint2(*)[SA])gsm;
    uint2 (*Bs0)[SB] = (uint2(*)[SB])(gsm + 128 * SA);
    uint2 (*As1)[SA] = (uint2(*)[SA])(gsm + GSTAGE);
    uint2 (*Bs1)[SB] = (uint2(*)[SB])(gsm + GSTAGE + 128 * SA);

    const int tid  = threadIdx.x;
    const int bm   = blockIdx.y * 128;
    const int bn   = blockIdx.x * 128;
    const int warp = tid >> 5, lane = tid & 31;
    const int g    = lane >> 2, tg = lane & 3;
    const int wm   = (warp >> 2) * 64;
    const int wn   = (warp & 3) * 32;

    float acc[4][4][4];
#pragma unroll
    for (int i = 0; i < 4; i++)
#pragma unroll
        for (int j = 0; j < 4; j++)
#pragma unroll
            for (int r = 0; r < 4; r++) acc[i][j][r] = 0.f;

    const int ar  = tid >> 3, ac4 = (tid & 7) * 4;
    const int akp = ac4 >> 1;
    const int bkp = tid >> 5, bc4 = (tid & 31) * 4;
    const float* Ag = A + (size_t)(bm + ar) * K + ac4;
    const float* Bg = B + (size_t)(2 * bkp) * N + bn + bc4;
    const int KT = K >> 5;

    float4 ra[4], rb[4];
#pragma unroll
    for (int i = 0; i < 4; i++) ra[i] = *(const float4*)(Ag + (size_t)(32 * i) * K);
    rb[0] = *(const float4*)(Bg);
    rb[1] = *(const float4*)(Bg + (size_t)N);
    rb[2] = *(const float4*)(Bg + (size_t)16 * N);
    rb[3] = *(const float4*)(Bg + (size_t)17 * N);
    gemm_store_tile(As0, Bs0, ra, rb, ar, akp, bkp, bc4);
    if (KT > 1) {
        const float* Ag2 = Ag + 32;
        const float* Bg2 = Bg + (size_t)32 * N;
#pragma unroll
        for (int i = 0; i < 4; i++) ra[i] = *(const float4*)(Ag2 + (size_t)(32 * i) * K);
        rb[0] = *(const float4*)(Bg2);
        rb[1] = *(const float4*)(Bg2 + (size_t)N);
        rb[2] = *(const float4*)(Bg2 + (size_t)16 * N);
        rb[3] = *(const float4*)(Bg2 + (size_t)17 * N);
    }
    __syncthreads();

    for (int kt = 0; kt < KT; kt++) {
        int cur = kt & 1;
        if (kt + 1 < KT)
            gemm_store_tile(cur ? As0 : As1, cur ? Bs0 : Bs1, ra, rb, ar, akp, bkp, bc4);
        if (kt + 2 < KT) {
            const float* Ag2 = Ag + (kt + 2) * 32;
            const float* Bg2 = Bg + (size_t)(kt + 2) * 32 * N;
#pragma unroll
            for (int i = 0; i < 4; i++) ra[i] = *(const float4*)(Ag2 + (size_t)(32 * i) * K);
            rb[0] = *(const float4*)(Bg2);
            rb[1] = *(const float4*)(Bg2 + (size_t)N);
            rb[2] = *(const float4*)(Bg2 + (size_t)16 * N);
            rb[3] = *(const float4*)(Bg2 + (size_t)17 * N);
        }
        gemm_compute_tile(cur ? As1 : As0, cur ? Bs1 : Bs0, acc, wm, wn, g, tg);
        __syncthreads();
    }

#pragma unroll
    for (int mt = 0; mt < 4; mt++) {
        int m = bm + wm + mt * 16 + g;
#pragma unroll
        for (int nt = 0; nt < 4; nt++) {
            int n = bn + wn + nt * 8 + tg * 2;
            float b0 = bias[n], b1 = bias[n + 1];
            float v00 = acc[mt][nt][0] + b0, v01 = acc[mt][nt][1] + b1;
            float v10 = acc[mt][nt][2] + b0, v11 = acc[mt][nt][3] + b1;
            if (MODE == 0) {
                C[(size_t)m * N + n]           = v00;
                C[(size_t)m * N + n + 1]       = v01;
                C[(size_t)(m + 8) * N + n]     = v10;
                C[(size_t)(m + 8) * N + n + 1] = v11;
            } else {
                int head = n >> 7, hd = n & 127;
                size_t b0i = ((size_t)head * SALL + tokoff + m) * HD + hd;
                size_t b1i = ((size_t)head * SALL + tokoff + m + 8) * HD + hd;
                C[b0i] = v00; C[b0i + 1] = v01;
                C[b1i] = v10; C[b1i + 1] = v11;
            }
        }
    }
}

// ---------------- RMSNorm + RoPE + pack ----------------
// QMODE 1: apply 1/sqrt(HD) scale, write g_qp[row][hdpair]
// QMODE 0: write g_kp[kvh][tile64][hdpair][key64] (transposed within 64-token tiles)
template <int QMODE>
__global__ __launch_bounds__(128) void norm_rope_pack(
    const float* __restrict__ x, const float* __restrict__ w,
    const float* __restrict__ aw, const float* __restrict__ rope)
{
    int row = blockIdx.x;            // head*SALL + token
    int token = row % SALL;
    int tid = threadIdx.x;

    float v = x[(size_t)row * HD + tid];
    float ss = v * v;
#pragma unroll
    for (int o = 16; o; o >>= 1) ss += __shfl_xor_sync(0xffffffffu, ss, o);
    __shared__ float red[4];
    if ((tid & 31) == 0) red[tid >> 5] = ss;
    __syncthreads();
    float tot = red[0] + red[1] + red[2] + red[3];
    float r = rsqrtf(tot * (1.0f / HD) + 1e-6f);
    float wt = (token < STXT) ? aw[tid] : w[tid];
    float xn = v * r * wt;

    float c = rope[(size_t)token * HD + tid];
    float s = rope[(size_t)(SALL + token) * HD + tid];
    float part = __shfl_xor_sync(0xffffffffu, xn, 1);
    float xr = (tid & 1) ? part : -part;
    float res = xn * c + xr * s;
    if (QMODE) res *= 0.08838834764831845f;   // 1/sqrt(128)

    float nb = __shfl_down_sync(0xffffffffu, res, 1);
    if ((tid & 1) == 0) {
        uint2 pkd = packsplit(res, nb);
        if (QMODE) {
            g_qp[(size_t)row * 64 + (tid >> 1)] = pkd;
        } else {
            int kvh = row / SALL;
            size_t idx = (((size_t)(kvh * NT64 + (token >> 6)) * 64) + (tid >> 1)) * 64
                         + (token & 63);
            g_kp[idx] = pkd;
        }
    }
}

// pack V: g_v float -> g_vp[kvh][tile64][keypair32][hd]
__global__ __launch_bounds__(128) void pack_v()
{
    int b = blockIdx.x;               // kvh*NT64*32 + tile*32 + kp
    int kp = b & 31;
    int tile = (b >> 5) % NT64;
    int kvh = b / (32 * NT64);
    int hd = threadIdx.x;
    const float* v0 = g_v + ((size_t)kvh * SALL + tile * 64 + 2 * kp) * HD + hd;
    float a = v0[0], c = v0[HD];
    g_vp[(((size_t)(kvh * NT64 + tile) * 32) + kp) * 128 + hd] = packsplit(a, c);
}

// ---------------- 3xBF16 flash attention: 128 q-rows/CTA, 64-key tiles, cp.async ----------------
// smem (uint2): uQ[128][68] | K0[64][68] | K1 | V0[32][132] | V1
#define OFF_K0 8704
#define OFF_K1 13056
#define OFF_V0 17408
#define OFF_V1 21632
#define FLASH_U2 25856

__device__ __forceinline__ void issue_kv(unsigned sbase, int koff, int voff,
                                         int kvh, int jt, int tid)
{
    const uint2* ksrc = g_kp + (size_t)(kvh * NT64 + jt) * 64 * 64;
    const uint2* vsrc = g_vp + (size_t)(kvh * NT64 + jt) * 32 * 128;
#pragma unroll
    for (int c = tid; c < 2048; c += 256) {
        int kr = c >> 5, kc = (c & 31) * 2;
        cpasync16(sbase + (unsigned)(koff + kr * 68 + kc) * 8, ksrc + kr * 64 + kc);
        int vr = c >> 6, vc = (c & 63) * 2;
        cpasync16(sbase + (unsigned)(voff + vr * 132 + vc) * 8, vsrc + vr * 128 + vc);
    }
    asm volatile("cp.async.commit_group;");
}

__global__ __launch_bounds__(256, 1) void flash_attn()
{
    extern __shared__ uint2 fsm[];
    unsigned sbase = (unsigned)__cvta_generic_to_shared(fsm);

    const int head = blockIdx.y;
    const int kvh  = head / (NH / NKVH);
    const int mb   = blockIdx.x * 128;
    const int tid  = threadIdx.x, lane = tid & 31;
    const int g    = lane >> 2, tg = lane & 3;
    const int m0   = (tid >> 5) * 16;

    // load Q tile (pre-packed)
    {
        const uint2* Qg = g_qp + ((size_t)head * SALL + mb) * 64;
        int r = tid >> 1, b = (tid & 1) * 32;
#pragma unroll
        for (int i = 0; i < 16; i++) {
            uint4 v = *(const uint4*)(Qg + (size_t)r * 64 + b + 2 * i);
            *(uint4*)&fsm[r * 68 + b + 2 * i] = v;
        }
    }

    // prologue: tile 0 -> buf0
    issue_kv(sbase, OFF_K0, OFF_V0, kvh, 0, tid);

    float o[16][4];
#pragma unroll
    for (int i = 0; i < 16; i++)
#pragma unroll
        for (int j = 0; j < 4; j++) o[i][j] = 0.f;
    float mprev0 = -INFINITY, mprev1 = -INFINITY, l0 = 0.f, l1 = 0.f;

    for (int jt = 0; jt < NT64; jt++) {
        int cur = jt & 1;
        if (jt + 1 < NT64) {
            issue_kv(sbase, cur ? OFF_K0 : OFF_K1, cur ? OFF_V0 : OFF_V1, kvh, jt + 1, tid);
            asm volatile("cp.async.wait_group 1;");
        } else {
            asm volatile("cp.async.wait_group 0;");
        }
        __syncthreads();

        const uint2* Kb = fsm + (cur ? OFF_K1 : OFF_K0);
        const uint2* Vb = fsm + (cur ? OFF_V1 : OFF_V0);

        // S = Q * K^T  (warp: 16 rows x 64 keys)
        float s[8][4];
#pragma unroll
        for (int nt = 0; nt < 8; nt++) { s[nt][0] = s[nt][1] = s[nt][2] = s[nt][3] = 0.f; }
#pragma unroll
        for (int kk = 0; kk < 8; kk++) {
            uint2 q0 = fsm[(m0 + g) * 68 + kk * 8 + tg];
            uint2 q1 = fsm[(m0 + g + 8) * 68 + kk * 8 + tg];
            uint2 q2 = fsm[(m0 + g) * 68 + kk * 8 + tg + 4];
            uint2 q3 = fsm[(m0 + g + 8) * 68 + kk * 8 + tg + 4];
            unsigned ah[4] = {q0.x, q1.x, q2.x, q3.x};
            unsigned al[4] = {q0.y, q1.y, q2.y, q3.y};
#pragma unroll
            for (int nt = 0; nt < 8; nt++) {
                uint2 k0 = Kb[(kk * 8 + tg) * 68 + nt * 8 + g];
                uint2 k1 = Kb[(kk * 8 + tg + 4) * 68 + nt * 8 + g];
                unsigned bh[2] = {k0.x, k1.x};
                unsigned bl[2] = {k0.y, k1.y};
                mma3b(s[nt], ah, al, bh, bl);
            }
        }

        // online softmax (rows g and g+8)
        float mx0 = -INFINITY, mx1 = -INFINITY;
#pragma unroll
        for (int nt = 0; nt < 8; nt++) {
            mx0 = fmaxf(mx0, fmaxf(s[nt][0], s[nt][1]));
            mx1 = fmaxf(mx1, fmaxf(s[nt][2], s[nt][3]));
        }
        mx0 = fmaxf(mx0, __shfl_xor_sync(0xffffffffu, mx0, 1));
        mx0 = fmaxf(mx0, __shfl_xor_sync(0xffffffffu, mx0, 2));
        mx1 = fmaxf(mx1, __shfl_xor_sync(0xffffffffu, mx1, 1));
        mx1 = fmaxf(mx1, __shfl_xor_sync(0xffffffffu, mx1, 2));

        float mn0 = fmaxf(mprev0, mx0), mn1 = fmaxf(mprev1, mx1);
        float al0 = __expf(mprev0 - mn0), al1 = __expf(mprev1 - mn1);
        // exp in place: s becomes P
        float sum0 = 0.f, sum1 = 0.f;
#pragma unroll
        for (int nt = 0; nt < 8; nt++) {
            s[nt][0] = __expf(s[nt][0] - mn0);
            s[nt][1] = __expf(s[nt][1] - mn0);
            s[nt][2] = __expf(s[nt][2] - mn1);
            s[nt][3] = __expf(s[nt][3] - mn1);
            sum0 += s[nt][0] + s[nt][1];
            sum1 += s[nt][2] + s[nt][3];
        }
        sum0 += __shfl_xor_sync(0xffffffffu, sum0, 1);
        sum0 += __shfl_xor_sync(0xffffffffu, sum0, 2);
        sum1 += __shfl_xor_sync(0xffffffffu, sum1, 1);
        sum1 += __shfl_xor_sync(0xffffffffu, sum1, 2);
        l0 = l0 * al0 + sum0;
        l1 = l1 * al1 + sum1;
        mprev0 = mn0; mprev1 = mn1;
        if (__any_sync(0xffffffffu, (al0 < 1.f) | (al1 < 1.f))) {
#pragma unroll
            for (int nt = 0; nt < 16; nt++) {
                o[nt][0] *= al0; o[nt][1] *= al0;
                o[nt][2] *= al1; o[nt][3] *= al1;
            }
        }

        // O += P * V (C-frag == A-frag layout; no shuffles). kk: 16 keys = S-tiles 2kk,2kk+1
#pragma unroll
        for (int kk = 0; kk < 4; kk++) {
            uint2 u0 = packsplit(s[2 * kk][0],     s[2 * kk][1]);
            uint2 u1 = packsplit(s[2 * kk][2],     s[2 * kk][3]);
            uint2 u2 = packsplit(s[2 * kk + 1][0], s[2 * kk + 1][1]);
            uint2 u3 = packsplit(s[2 * kk + 1][2], s[2 * kk + 1][3]);
            unsigned ah[4] = {u0.x, u1.x, u2.x, u3.x};
            unsigned al2[4] = {u0.y, u1.y, u2.y, u3.y};
#pragma unroll
            for (int nt = 0; nt < 16; nt++) {
                uint2 v0 = Vb[(kk * 8 + tg) * 132 + nt * 8 + g];
                uint2 v1 = Vb[(kk * 8 + tg + 4) * 132 + nt * 8 + g];
                unsigned bh[2] = {v0.x, v1.x};
                unsigned bl[2] = {v0.y, v1.y};
                mma3b(o[nt], ah, al2, bh, bl);
            }
        }
        __syncthreads();  // done reading this buffer before next issue overwrites it
    }

    // write out: g_ao[token][head*HD + col]
    float r0 = 1.f / l0, r1 = 1.f / l1;
    int tok0 = mb + m0 + g;
#pragma unroll
    for (int nt = 0; nt < 16; nt++) {
        int col = head * HD + nt * 8 + 2 * tg;
        float2 v0 = make_float2(o[nt][0] * r0, o[nt][1] * r0);
        float2 v1 = make_float2(o[nt][2] * r1, o[nt][3] * r1);
        *(float2*)&g_ao[(size_t)tok0 * DMODEL + col]       = v0;
        *(float2*)&g_ao[(size_t)(tok0 + 8) * DMODEL + col] = v1;
    }
}

// ---------------- launch ----------------
#define GEMM_SMEM  (2 * GSTAGE * 8)        // 74752
#define FLASH_SMEM (FLASH_U2 * 8)          // 206848

extern "C" void kernel_launch(void* const* d_in, const int* in_sizes, int n_in,
                              void* d_out, int out_size)
{
    const float* hs    = (const float*)d_in[0];
    const float* enc   = (const float*)d_in[1];
    const float* rope  = (const float*)d_in[2];
    const float* Wq    = (const float*)d_in[3];
    const float* bq    = (const float*)d_in[4];
    const float* Wk    = (const float*)d_in[5];
    const float* bk    = (const float*)d_in[6];
    const float* Wv    = (const float*)d_in[7];
    const float* bv    = (const float*)d_in[8];
    const float* aWq   = (const float*)d_in[9];
    const float* abq   = (const float*)d_in[10];
    const float* aWk   = (const float*)d_in[11];
    const float* abk   = (const float*)d_in[12];
    const float* aWv   = (const float*)d_in[13];
    const float* abv   = (const float*)d_in[14];
    const float* nq    = (const float*)d_in[15];
    const float* nk    = (const float*)d_in[16];
    const float* anq   = (const float*)d_in[17];
    const float* ank   = (const float*)d_in[18];
    const float* Wout  = (const float*)d_in[19];
    const float* bout  = (const float*)d_in[20];
    const float* Waout = (const float*)d_in[21];
    const float* baout = (const float*)d_in[22];
    float* out = (float*)d_out;

    float *pq, *pk_, *pv, *pao;
    cudaGetSymbolAddress((void**)&pq, g_q);
    cudaGetSymbolAddress((void**)&pk_, g_k);
    cudaGetSymbolAddress((void**)&pv, g_v);
    cudaGetSymbolAddress((void**)&pao, g_ao);

    cudaFuncSetAttribute(gemm_bf16<0>, cudaFuncAttributeMaxDynamicSharedMemorySize, GEMM_SMEM);
    cudaFuncSetAttribute(gemm_bf16<1>, cudaFuncAttributeMaxDynamicSharedMemorySize, GEMM_SMEM);
    cudaFuncSetAttribute(flash_attn,   cudaFuncAttributeMaxDynamicSharedMemorySize, FLASH_SMEM);

    // QKV projections (image stream -> tokens 512.., text stream -> tokens 0..511)
    gemm_bf16<1><<<dim3(24, 32), 256, GEMM_SMEM>>>(hs,  Wq,  bq,  pq,  SIMG, NH * HD,   DMODEL, STXT);
    gemm_bf16<1><<<dim3(8,  32), 256, GEMM_SMEM>>>(hs,  Wk,  bk,  pk_, SIMG, NKVH * HD, DMODEL, STXT);
    gemm_bf16<1><<<dim3(8,  32), 256, GEMM_SMEM>>>(hs,  Wv,  bv,  pv,  SIMG, NKVH * HD, DMODEL, STXT);
    gemm_bf16<1><<<dim3(24, 4),  256, GEMM_SMEM>>>(enc, aWq, abq, pq,  STXT, NH * HD,   DMODEL, 0);
    gemm_bf16<1><<<dim3(8,  4),  256, GEMM_SMEM>>>(enc, aWk, abk, pk_, STXT, NKVH * HD, DMODEL, 0);
    gemm_bf16<1><<<dim3(8,  4),  256, GEMM_SMEM>>>(enc, aWv, abv, pv,  STXT, NKVH * HD, DMODEL, 0);

    // RMSNorm + RoPE + pack (q scaled), and V pack
    norm_rope_pack<1><<<NH * SALL,   128>>>(pq,  nq, anq, rope);
    norm_rope_pack<0><<<NKVH * SALL, 128>>>(pk_, nk, ank, rope);
    pack_v<<<NKVH * NT64 * 32, 128>>>();

    // attention
    flash_attn<<<dim3(SALL / 128, NH), 256, FLASH_SMEM>>>();

    // output projections: hid (image rows 512..4607) first, then enc (text rows 0..511)
    gemm_bf16<0><<<dim3(24, 32), 256, GEMM_SMEM>>>(pao + (size_t)STXT * DMODEL, Wout, bout,
                                                   out, SIMG, DMODEL, DMODEL, 0);
    gemm_bf16<0><<<dim3(24, 4), 256, GEMM_SMEM>>>(pao, Waout, baout,
                                                  out + (size_t)SIMG * DMODEL, STXT, DMODEL, DMODEL, 0);
}

// round 9
// speedup vs baseline: 2.7253x; 1.0994x over previous
#include <cuda_runtime.h>
#include <math.h>

#define NH     24
#define NKVH   8
#define HD     128
#define STXT   512
#define SIMG   4096
#define SALL   4608
#define DMODEL 3072
#define NT64   72           // SALL/64 key tiles
#define KT96   96           // DMODEL/32 k-tiles

// ---------------- scratch (device globals: allocation-free) ----------------
__device__ float g_q[(size_t)NH * SALL * HD];     // [head][token][hd] (pre-norm)
__device__ float g_k[(size_t)NKVH * SALL * HD];
__device__ float g_v[(size_t)NKVH * SALL * HD];
__device__ float g_ao[(size_t)SALL * DMODEL];     // [token][h*HD+hd]
// packed bf16 hi/lo operand buffers for flash attention
__device__ uint2 g_qp[(size_t)NH * SALL * 64];            // [head][token][hdpair]
__device__ uint2 g_kp[(size_t)NKVH * NT64 * 64 * 64];     // [kvh][tile][hdpair][key64]
__device__ uint2 g_vp[(size_t)NKVH * NT64 * 32 * 128];    // [kvh][tile][keypair32][hd]
// packed GEMM operand images (A: [mtile][ktile][row128][kpair16 pad20],
//                             B: [ntile][ktile][kpair16][col128 pad132])
#define ATILE 2560
#define BTILE 2112
#define AIMG_HS   ((size_t)0)
#define AIMG_ENC  (AIMG_HS  + (size_t)32 * KT96 * ATILE)
#define AIMG_AOH  (AIMG_ENC + (size_t)4  * KT96 * ATILE)
#define AIMG_AOT  (AIMG_AOH + (size_t)32 * KT96 * ATILE)
#define AIMG_TOT  (AIMG_AOT + (size_t)4  * KT96 * ATILE)
__device__ uint2 g_aimg[AIMG_TOT];
#define BIMG_Q    ((size_t)0)
#define BIMG_K    (BIMG_Q  + (size_t)24 * KT96 * BTILE)
#define BIMG_V    (BIMG_K  + (size_t)8  * KT96 * BTILE)
#define BIMG_AQ   (BIMG_V  + (size_t)8  * KT96 * BTILE)
#define BIMG_AK   (BIMG_AQ + (size_t)24 * KT96 * BTILE)
#define BIMG_AV   (BIMG_AK + (size_t)8  * KT96 * BTILE)
#define BIMG_O    (BIMG_AV + (size_t)8  * KT96 * BTILE)
#define BIMG_AO   (BIMG_O  + (size_t)24 * KT96 * BTILE)
#define BIMG_TOT  (BIMG_AO + (size_t)24 * KT96 * BTILE)
__device__ uint2 g_bimg[BIMG_TOT];

// ---------------- helpers ----------------
__device__ __forceinline__ unsigned pk(float a, float b) {
    unsigned r;
    asm("cvt.rn.bf16x2.f32 %0, %1, %2;" : "=r"(r) : "f"(b), "f"(a));
    return r;
}
__device__ __forceinline__ uint2 packsplit(float a, float b) {
    uint2 r;
    r.x = pk(a, b);
    float ha = __uint_as_float(r.x << 16);
    float hb = __uint_as_float(r.x & 0xffff0000u);
    r.y = pk(a - ha, b - hb);
    return r;
}
__device__ __forceinline__ void mma16(float* c, const unsigned* a, const unsigned* b) {
    asm volatile(
        "mma.sync.aligned.m16n8k16.row.col.f32.bf16.bf16.f32 "
        "{%0,%1,%2,%3},{%4,%5,%6,%7},{%8,%9},{%0,%1,%2,%3};"
        : "+f"(c[0]), "+f"(c[1]), "+f"(c[2]), "+f"(c[3])
        : "r"(a[0]), "r"(a[1]), "r"(a[2]), "r"(a[3]), "r"(b[0]), "r"(b[1]));
}
__device__ __forceinline__ void mma3b(float* c, const unsigned* ah, const unsigned* al,
                                      const unsigned* bh, const unsigned* bl) {
    mma16(c, al, bh);
    mma16(c, ah, bl);
    mma16(c, ah, bh);
}
__device__ __forceinline__ void cpasync16(unsigned dst, const void* src) {
    asm volatile("cp.async.cg.shared.global [%0], [%1], 16;" :: "r"(dst), "l"(src));
}

// ---------------- operand pack kernels ----------------
// A image: per (mi,kt): uint2[128][20]; A fp32 [M,K] row-major (ptr may be pre-offset)
__global__ __launch_bounds__(256) void pack_a(const float* __restrict__ A,
                                              uint2* __restrict__ dst, int K)
{
    int mi = blockIdx.x, kt = blockIdx.y, nkt = gridDim.y;
    int tid = threadIdx.x;
    int kp = tid & 15, r0 = tid >> 4;
    uint2* d = dst + ((size_t)mi * nkt + kt) * ATILE;
    const float* s = A + (size_t)(mi * 128) * K + kt * 32 + kp * 2;
#pragma unroll
    for (int i = 0; i < 8; i++) {
        int r = r0 + i * 16;
        float2 v = *(const float2*)(s + (size_t)r * K);
        d[r * 20 + kp] = packsplit(v.x, v.y);
    }
}

// B image: per (ni,kt): uint2[16][132]; B fp32 [K,N] row-major
__global__ __launch_bounds__(256) void pack_b(const float* __restrict__ B,
                                              uint2* __restrict__ dst, int N)
{
    int ni = blockIdx.x, kt = blockIdx.y, nkt = gridDim.y;
    int tid = threadIdx.x;
    int c = tid & 127, kg = tid >> 7;
    uint2* d = dst + ((size_t)ni * nkt + kt) * BTILE;
    const float* s = B + (size_t)(kt * 32) * N + ni * 128 + c;
#pragma unroll
    for (int i = 0; i < 8; i++) {
        int kp = kg * 8 + i;
        float a = s[(size_t)(2 * kp) * N];
        float b = s[(size_t)(2 * kp + 1) * N];
        d[kp * 132 + c] = packsplit(a, b);
    }
}

// ---------------- GEMM from packed images, cp.async double-buffered ----------------
#define GST 4672   // uint2 per stage (2560 A + 2112 B)

__device__ __forceinline__ void gcopy(unsigned sb, int stage,
                                      const uint2* __restrict__ Aimg,
                                      const uint2* __restrict__ Bimg,
                                      int atile, int btile, int tid)
{
    unsigned abase = sb + stage * (GST * 8);
    const uint2* as = Aimg + (size_t)atile * ATILE;
#pragma unroll
    for (int i = 0; i < 5; i++) {
        int c = tid + i * 256;                 // 1280 chunks of 16B
        cpasync16(abase + c * 16, as + c * 2);
    }
    unsigned bbase = abase + ATILE * 8;
    const uint2* bs = Bimg + (size_t)btile * BTILE;
#pragma unroll
    for (int i = 0; i < 5; i++) {
        int c = tid + i * 256;                 // 1056 chunks of 16B
        if (c < 1056) cpasync16(bbase + c * 16, bs + c * 2);
    }
    asm volatile("cp.async.commit_group;");
}

__device__ __forceinline__ void gcompute(const uint2* st, float acc[4][4][4],
                                         int wm, int wn, int g, int tg)
{
    const uint2 (*As)[20]  = (const uint2(*)[20])st;
    const uint2 (*Bs)[132] = (const uint2(*)[132])(st + ATILE);
#pragma unroll
    for (int kk = 0; kk < 2; kk++) {
        unsigned ah[4][4], al[4][4], bh[4][2], bl[4][2];
#pragma unroll
        for (int mt = 0; mt < 4; mt++) {
            int m0 = wm + mt * 16;
            uint2 q0 = As[m0 + g][kk * 8 + tg];
            uint2 q1 = As[m0 + g + 8][kk * 8 + tg];
            uint2 q2 = As[m0 + g][kk * 8 + tg + 4];
            uint2 q3 = As[m0 + g + 8][kk * 8 + tg + 4];
            ah[mt][0] = q0.x; ah[mt][1] = q1.x; ah[mt][2] = q2.x; ah[mt][3] = q3.x;
            al[mt][0] = q0.y; al[mt][1] = q1.y; al[mt][2] = q2.y; al[mt][3] = q3.y;
        }
#pragma unroll
        for (int nt = 0; nt < 4; nt++) {
            int n0 = wn + nt * 8;
            uint2 c0 = Bs[kk * 8 + tg][n0 + g];
            uint2 c1 = Bs[kk * 8 + tg + 4][n0 + g];
            bh[nt][0] = c0.x; bh[nt][1] = c1.x;
            bl[nt][0] = c0.y; bl[nt][1] = c1.y;
        }
#pragma unroll
        for (int mt = 0; mt < 4; mt++)
#pragma unroll
            for (int nt = 0; nt < 4; nt++)
                mma3b(acc[mt][nt], ah[mt], al[mt], bh[nt], bl[nt]);
    }
}

// MODE 0: C row-major [M,N].  MODE 1: scatter head-major (see epilogue).
template <int MODE>
__global__ __launch_bounds__(256, 2) void gemm_pk(
    const uint2* __restrict__ Aimg, const uint2* __restrict__ Bimg,
    const float* __restrict__ bias, float* __restrict__ C,
    int N, int KT, int tokoff)
{
    extern __shared__ uint2 gsm[];
    unsigned sb = (unsigned)__cvta_generic_to_shared(gsm);

    const int tid  = threadIdx.x;
    const int mi   = blockIdx.y;
    const int ni   = blockIdx.x;
    const int warp = tid >> 5, lane = tid & 31;
    const int g    = lane >> 2, tg = lane & 3;
    const int wm   = (warp >> 2) * 64;
    const int wn   = (warp & 3) * 32;

    const int abase = mi * KT, bbase = ni * KT;

    float acc[4][4][4];
#pragma unroll
    for (int i = 0; i < 4; i++)
#pragma unroll
        for (int j = 0; j < 4; j++)
#pragma unroll
            for (int r = 0; r < 4; r++) acc[i][j][r] = 0.f;

    gcopy(sb, 0, Aimg, Bimg, abase + 0, bbase + 0, tid);
    if (KT > 1) gcopy(sb, 1, Aimg, Bimg, abase + 1, bbase + 1, tid);

    for (int kt = 0; kt < KT; kt++) {
        if (kt < KT - 1) asm volatile("cp.async.wait_group 1;");
        else             asm volatile("cp.async.wait_group 0;");
        __syncthreads();
        gcompute(gsm + (kt & 1) * GST, acc, wm, wn, g, tg);
        __syncthreads();
        if (kt + 2 < KT)
            gcopy(sb, kt & 1, Aimg, Bimg, abase + kt + 2, bbase + kt + 2, tid);
    }

    // epilogue
#pragma unroll
    for (int mt = 0; mt < 4; mt++) {
        int m = mi * 128 + wm + mt * 16 + g;
#pragma unroll
        for (int nt = 0; nt < 4; nt++) {
            int n = ni * 128 + wn + nt * 8 + tg * 2;
            float b0 = bias[n], b1 = bias[n + 1];
            float v00 = acc[mt][nt][0] + b0, v01 = acc[mt][nt][1] + b1;
            float v10 = acc[mt][nt][2] + b0, v11 = acc[mt][nt][3] + b1;
            if (MODE == 0) {
                C[(size_t)m * N + n]           = v00;
                C[(size_t)m * N + n + 1]       = v01;
                C[(size_t)(m + 8) * N + n]     = v10;
                C[(size_t)(m + 8) * N + n + 1] = v11;
            } else {
                int head = n >> 7, hd = n & 127;
                size_t b0i = ((size_t)head * SALL + tokoff + m) * HD + hd;
                size_t b1i = ((size_t)head * SALL + tokoff + m + 8) * HD + hd;
                C[b0i] = v00; C[b0i + 1] = v01;
                C[b1i] = v10; C[b1i + 1] = v11;
            }
        }
    }
}

// ---------------- RMSNorm + RoPE + pack (R7, proven) ----------------
template <int QMODE>
__global__ __launch_bounds__(128) void norm_rope_pack(
    const float* __restrict__ x, const float* __restrict__ w,
    const float* __restrict__ aw, const float* __restrict__ rope)
{
    int row = blockIdx.x;            // head*SALL + token
    int token = row % SALL;
    int tid = threadIdx.x;

    float v = x[(size_t)row * HD + tid];
    float ss = v * v;
#pragma unroll
    for (int o = 16; o; o >>= 1) ss += __shfl_xor_sync(0xffffffffu, ss, o);
    __shared__ float red[4];
    if ((tid & 31) == 0) red[tid >> 5] = ss;
    __syncthreads();
    float tot = red[0] + red[1] + red[2] + red[3];
    float r = rsqrtf(tot * (1.0f / HD) + 1e-6f);
    float wt = (token < STXT) ? aw[tid] : w[tid];
    float xn = v * r * wt;

    float c = rope[(size_t)token * HD + tid];
    float s = rope[(size_t)(SALL + token) * HD + tid];
    float part = __shfl_xor_sync(0xffffffffu, xn, 1);
    float xr = (tid & 1) ? part : -part;
    float res = xn * c + xr * s;
    if (QMODE) res *= 0.08838834764831845f;   // 1/sqrt(128)

    float nb = __shfl_down_sync(0xffffffffu, res, 1);
    if ((tid & 1) == 0) {
        uint2 pkd = packsplit(res, nb);
        if (QMODE) {
            g_qp[(size_t)row * 64 + (tid >> 1)] = pkd;
        } else {
            int kvh = row / SALL;
            size_t idx = (((size_t)(kvh * NT64 + (token >> 6)) * 64) + (tid >> 1)) * 64
                         + (token & 63);
            g_kp[idx] = pkd;
        }
    }
}

__global__ __launch_bounds__(128) void pack_v()
{
    int b = blockIdx.x;
    int kp = b & 31;
    int tile = (b >> 5) % NT64;
    int kvh = b / (32 * NT64);
    int hd = threadIdx.x;
    const float* v0 = g_v + ((size_t)kvh * SALL + tile * 64 + 2 * kp) * HD + hd;
    float a = v0[0], c = v0[HD];
    g_vp[(((size_t)(kvh * NT64 + tile) * 32) + kp) * 128 + hd] = packsplit(a, c);
}

// ---------------- 3xBF16 flash attention (R7, proven) ----------------
#define OFF_K0 8704
#define OFF_K1 13056
#define OFF_V0 17408
#define OFF_V1 21632
#define FLASH_U2 25856

__device__ __forceinline__ void issue_kv(unsigned sbase, int koff, int voff,
                                         int kvh, int jt, int tid)
{
    const uint2* ksrc = g_kp + (size_t)(kvh * NT64 + jt) * 64 * 64;
    const uint2* vsrc = g_vp + (size_t)(kvh * NT64 + jt) * 32 * 128;
#pragma unroll
    for (int c = tid; c < 2048; c += 256) {
        int kr = c >> 5, kc = (c & 31) * 2;
        cpasync16(sbase + (unsigned)(koff + kr * 68 + kc) * 8, ksrc + kr * 64 + kc);
        int vr = c >> 6, vc = (c & 63) * 2;
        cpasync16(sbase + (unsigned)(voff + vr * 132 + vc) * 8, vsrc + vr * 128 + vc);
    }
    asm volatile("cp.async.commit_group;");
}

__global__ __launch_bounds__(256, 1) void flash_attn()
{
    extern __shared__ uint2 fsm[];
    unsigned sbase = (unsigned)__cvta_generic_to_shared(fsm);

    const int head = blockIdx.y;
    const int kvh  = head / (NH / NKVH);
    const int mb   = blockIdx.x * 128;
    const int tid  = threadIdx.x, lane = tid & 31;
    const int g    = lane >> 2, tg = lane & 3;
    const int m0   = (tid >> 5) * 16;

    {
        const uint2* Qg = g_qp + ((size_t)head * SALL + mb) * 64;
        int r = tid >> 1, b = (tid & 1) * 32;
#pragma unroll
        for (int i = 0; i < 16; i++) {
            uint4 v = *(const uint4*)(Qg + (size_t)r * 64 + b + 2 * i);
            *(uint4*)&fsm[r * 68 + b + 2 * i] = v;
        }
    }

    issue_kv(sbase, OFF_K0, OFF_V0, kvh, 0, tid);

    float o[16][4];
#pragma unroll
    for (int i = 0; i < 16; i++)
#pragma unroll
        for (int j = 0; j < 4; j++) o[i][j] = 0.f;
    float mprev0 = -INFINITY, mprev1 = -INFINITY, l0 = 0.f, l1 = 0.f;

    for (int jt = 0; jt < NT64; jt++) {
        int cur = jt & 1;
        if (jt + 1 < NT64) {
            issue_kv(sbase, cur ? OFF_K0 : OFF_K1, cur ? OFF_V0 : OFF_V1, kvh, jt + 1, tid);
            asm volatile("cp.async.wait_group 1;");
        } else {
            asm volatile("cp.async.wait_group 0;");
        }
        __syncthreads();

        const uint2* Kb = fsm + (cur ? OFF_K1 : OFF_K0);
        const uint2* Vb = fsm + (cur ? OFF_V1 : OFF_V0);

        float s[8][4];
#pragma unroll
        for (int nt = 0; nt < 8; nt++) { s[nt][0] = s[nt][1] = s[nt][2] = s[nt][3] = 0.f; }
#pragma unroll
        for (int kk = 0; kk < 8; kk++) {
            uint2 q0 = fsm[(m0 + g) * 68 + kk * 8 + tg];
            uint2 q1 = fsm[(m0 + g + 8) * 68 + kk * 8 + tg];
            uint2 q2 = fsm[(m0 + g) * 68 + kk * 8 + tg + 4];
            uint2 q3 = fsm[(m0 + g + 8) * 68 + kk * 8 + tg + 4];
            unsigned ah[4] = {q0.x, q1.x, q2.x, q3.x};
            unsigned al[4] = {q0.y, q1.y, q2.y, q3.y};
#pragma unroll
            for (int nt = 0; nt < 8; nt++) {
                uint2 k0 = Kb[(kk * 8 + tg) * 68 + nt * 8 + g];
                uint2 k1 = Kb[(kk * 8 + tg + 4) * 68 + nt * 8 + g];
                unsigned bh[2] = {k0.x, k1.x};
                unsigned bl[2] = {k0.y, k1.y};
                mma3b(s[nt], ah, al, bh, bl);
            }
        }

        float mx0 = -INFINITY, mx1 = -INFINITY;
#pragma unroll
        for (int nt = 0; nt < 8; nt++) {
            mx0 = fmaxf(mx0, fmaxf(s[nt][0], s[nt][1]));
            mx1 = fmaxf(mx1, fmaxf(s[nt][2], s[nt][3]));
        }
        mx0 = fmaxf(mx0, __shfl_xor_sync(0xffffffffu, mx0, 1));
        mx0 = fmaxf(mx0, __shfl_xor_sync(0xffffffffu, mx0, 2));
        mx1 = fmaxf(mx1, __shfl_xor_sync(0xffffffffu, mx1, 1));
        mx1 = fmaxf(mx1, __shfl_xor_sync(0xffffffffu, mx1, 2));

        float mn0 = fmaxf(mprev0, mx0), mn1 = fmaxf(mprev1, mx1);
        float al0 = __expf(mprev0 - mn0), al1 = __expf(mprev1 - mn1);
        float sum0 = 0.f, sum1 = 0.f;
#pragma unroll
        for (int nt = 0; nt < 8; nt++) {
            s[nt][0] = __expf(s[nt][0] - mn0);
            s[nt][1] = __expf(s[nt][1] - mn0);
            s[nt][2] = __expf(s[nt][2] - mn1);
            s[nt][3] = __expf(s[nt][3] - mn1);
            sum0 += s[nt][0] + s[nt][1];
            sum1 += s[nt][2] + s[nt][3];
        }
        sum0 += __shfl_xor_sync(0xffffffffu, sum0, 1);
        sum0 += __shfl_xor_sync(0xffffffffu, sum0, 2);
        sum1 += __shfl_xor_sync(0xffffffffu, sum1, 1);
        sum1 += __shfl_xor_sync(0xffffffffu, sum1, 2);
        l0 = l0 * al0 + sum0;
        l1 = l1 * al1 + sum1;
        mprev0 = mn0; mprev1 = mn1;
        if (__any_sync(0xffffffffu, (al0 < 1.f) | (al1 < 1.f))) {
#pragma unroll
            for (int nt = 0; nt < 16; nt++) {
                o[nt][0] *= al0; o[nt][1] *= al0;
                o[nt][2] *= al1; o[nt][3] *= al1;
            }
        }

#pragma unroll
        for (int kk = 0; kk < 4; kk++) {
            uint2 u0 = packsplit(s[2 * kk][0],     s[2 * kk][1]);
            uint2 u1 = packsplit(s[2 * kk][2],     s[2 * kk][3]);
            uint2 u2 = packsplit(s[2 * kk + 1][0], s[2 * kk + 1][1]);
            uint2 u3 = packsplit(s[2 * kk + 1][2], s[2 * kk + 1][3]);
            unsigned ah[4] = {u0.x, u1.x, u2.x, u3.x};
            unsigned al2[4] = {u0.y, u1.y, u2.y, u3.y};
#pragma unroll
            for (int nt = 0; nt < 16; nt++) {
                uint2 v0 = Vb[(kk * 8 + tg) * 132 + nt * 8 + g];
                uint2 v1 = Vb[(kk * 8 + tg + 4) * 132 + nt * 8 + g];
                unsigned bh[2] = {v0.x, v1.x};
                unsigned bl[2] = {v0.y, v1.y};
                mma3b(o[nt], ah, al2, bh, bl);
            }
        }
        __syncthreads();
    }

    float r0 = 1.f / l0, r1 = 1.f / l1;
    int tok0 = mb + m0 + g;
#pragma unroll
    for (int nt = 0; nt < 16; nt++) {
        int col = head * HD + nt * 8 + 2 * tg;
        float2 v0 = make_float2(o[nt][0] * r0, o[nt][1] * r0);
        float2 v1 = make_float2(o[nt][2] * r1, o[nt][3] * r1);
        *(float2*)&g_ao[(size_t)tok0 * DMODEL + col]       = v0;
        *(float2*)&g_ao[(size_t)(tok0 + 8) * DMODEL + col] = v1;
    }
}

// ---------------- launch ----------------
#define GEMM_SMEM  (2 * GST * 8)           // 74752
#define FLASH_SMEM (FLASH_U2 * 8)          // 206848

extern "C" void kernel_launch(void* const* d_in, const int* in_sizes, int n_in,
                              void* d_out, int out_size)
{
    const float* hs    = (const float*)d_in[0];
    const float* enc   = (const float*)d_in[1];
    const float* rope  = (const float*)d_in[2];
    const float* Wq    = (const float*)d_in[3];
    const float* bq    = (const float*)d_in[4];
    const float* Wk    = (const float*)d_in[5];
    const float* bk    = (const float*)d_in[6];
    const float* Wv    = (const float*)d_in[7];
    const float* bv    = (const float*)d_in[8];
    const float* aWq   = (const float*)d_in[9];
    const float* abq   = (const float*)d_in[10];
    const float* aWk   = (const float*)d_in[11];
    const float* abk   = (const float*)d_in[12];
    const float* aWv   = (const float*)d_in[13];
    const float* abv   = (const float*)d_in[14];
    const float* nq    = (const float*)d_in[15];
    const float* nk    = (const float*)d_in[16];
    const float* anq   = (const float*)d_in[17];
    const float* ank   = (const float*)d_in[18];
    const float* Wout  = (const float*)d_in[19];
    const float* bout  = (const float*)d_in[20];
    const float* Waout = (const float*)d_in[21];
    const float* baout = (const float*)d_in[22];
    float* out = (float*)d_out;

    float *pq, *pk_, *pv, *pao;
    uint2 *pai, *pbi;
    cudaGetSymbolAddress((void**)&pq,  g_q);
    cudaGetSymbolAddress((void**)&pk_, g_k);
    cudaGetSymbolAddress((void**)&pv,  g_v);
    cudaGetSymbolAddress((void**)&pao, g_ao);
    cudaGetSymbolAddress((void**)&pai, g_aimg);
    cudaGetSymbolAddress((void**)&pbi, g_bimg);

    cudaFuncSetAttribute(gemm_pk<0>, cudaFuncAttributeMaxDynamicSharedMemorySize, GEMM_SMEM);
    cudaFuncSetAttribute(gemm_pk<1>, cudaFuncAttributeMaxDynamicSharedMemorySize, GEMM_SMEM);
    cudaFuncSetAttribute(flash_attn, cudaFuncAttributeMaxDynamicSharedMemorySize, FLASH_SMEM);

    // ---- pack weights + input activations ----
    pack_b<<<dim3(24, KT96), 256>>>(Wq,  pbi + BIMG_Q,  NH * HD);
    pack_b<<<dim3(8,  KT96), 256>>>(Wk,  pbi + BIMG_K,  NKVH * HD);
    pack_b<<<dim3(8,  KT96), 256>>>(Wv,  pbi + BIMG_V,  NKVH * HD);
    pack_b<<<dim3(24, KT96), 256>>>(aWq, pbi + BIMG_AQ, NH * HD);
    pack_b<<<dim3(8,  KT96), 256>>>(aWk, pbi + BIMG_AK, NKVH * HD);
    pack_b<<<dim3(8,  KT96), 256>>>(aWv, pbi + BIMG_AV, NKVH * HD);
    pack_b<<<dim3(24, KT96), 256>>>(Wout,  pbi + BIMG_O,  DMODEL);
    pack_b<<<dim3(24, KT96), 256>>>(Waout, pbi + BIMG_AO, DMODEL);
    pack_a<<<dim3(32, KT96), 256>>>(hs,  pai + AIMG_HS,  DMODEL);
    pack_a<<<dim3(4,  KT96), 256>>>(enc, pai + AIMG_ENC, DMODEL);

    // ---- QKV projections ----
    gemm_pk<1><<<dim3(24, 32), 256, GEMM_SMEM>>>(pai + AIMG_HS,  pbi + BIMG_Q,  bq,  pq,  NH * HD,   KT96, STXT);
    gemm_pk<1><<<dim3(8,  32), 256, GEMM_SMEM>>>(pai + AIMG_HS,  pbi + BIMG_K,  bk,  pk_, NKVH * HD, KT96, STXT);
    gemm_pk<1><<<dim3(8,  32), 256, GEMM_SMEM>>>(pai + AIMG_HS,  pbi + BIMG_V,  bv,  pv,  NKVH * HD, KT96, STXT);
    gemm_pk<1><<<dim3(24, 4),  256, GEMM_SMEM>>>(pai + AIMG_ENC, pbi + BIMG_AQ, abq, pq,  NH * HD,   KT96, 0);
    gemm_pk<1><<<dim3(8,  4),  256, GEMM_SMEM>>>(pai + AIMG_ENC, pbi + BIMG_AK, abk, pk_, NKVH * HD, KT96, 0);
    gemm_pk<1><<<dim3(8,  4),  256, GEMM_SMEM>>>(pai + AIMG_ENC, pbi + BIMG_AV, abv, pv,  NKVH * HD, KT96, 0);

    // ---- RMSNorm + RoPE + pack, V pack ----
    norm_rope_pack<1><<<NH * SALL,   128>>>(pq,  nq, anq, rope);
    norm_rope_pack<0><<<NKVH * SALL, 128>>>(pk_, nk, ank, rope);
    pack_v<<<NKVH * NT64 * 32, 128>>>();

    // ---- attention ----
    flash_attn<<<dim3(SALL / 128, NH), 256, FLASH_SMEM>>>();

    // ---- pack attention output, final projections ----
    pack_a<<<dim3(32, KT96), 256>>>(pao + (size_t)STXT * DMODEL, pai + AIMG_AOH, DMODEL);
    pack_a<<<dim3(4,  KT96), 256>>>(pao,                         pai + AIMG_AOT, DMODEL);
    gemm_pk<0><<<dim3(24, 32), 256, GEMM_SMEM>>>(pai + AIMG_AOH, pbi + BIMG_O,  bout,  out,
                                                 DMODEL, KT96, 0);
    gemm_pk<0><<<dim3(24, 4),  256, GEMM_SMEM>>>(pai + AIMG_AOT, pbi + BIMG_AO, baout,
                                                 out + (size_t)SIMG * DMODEL, DMODEL, KT96, 0);
}

// round 15
// speedup vs baseline: 3.0969x; 1.1363x over previous
#include <cuda_runtime.h>
#include <math.h>

#define NH     24
#define NKVH   8
#define HD     128
#define STXT   512
#define SIMG   4096
#define SALL   4608
#define DMODEL 3072
#define NT64   72           // SALL/64 key tiles
#define KT96   96           // DMODEL/32 k-tiles

// ---------------- scratch (device globals: allocation-free) ----------------
__device__ float g_q[(size_t)NH * SALL * HD];     // [head][token][hd] (pre-norm)
__device__ float g_k[(size_t)NKVH * SALL * HD];
__device__ float g_v[(size_t)NKVH * SALL * HD];
__device__ float g_ao[(size_t)SALL * DMODEL];     // [token][h*HD+hd]
// packed bf16 hi/lo operand buffers for flash attention
__device__ uint2 g_qp[(size_t)NH * SALL * 64];            // [head][token][hdpair]
__device__ uint2 g_kp[(size_t)NKVH * NT64 * 64 * 64];     // [kvh][tile][hdpair][key64]
__device__ uint2 g_vp[(size_t)NKVH * NT64 * 32 * 128];    // [kvh][tile][keypair32][hd]
// packed GEMM operand images
#define ATILE 2560
#define BTILE 2112
// A images: HS(32) | ENC(4) | AOH(32) | AOT(4) mtiles, each [KT96][ATILE]
#define AIMG_QKV  ((size_t)0)                              // 36 mtiles (HS+ENC)
#define AIMG_AO   ((size_t)36 * KT96 * ATILE)              // 36 mtiles (AOH+AOT)
#define AIMG_TOT  ((size_t)72 * KT96 * ATILE)
__device__ uint2 g_aimg[AIMG_TOT];
// B images: Q(24)|K(8)|V(8)|AQ(24)|AK(8)|AV(8)|O(24)|AO(24) = 128 ntiles
#define BN_QKV  0      // ni 0..39  : Q|K|V
#define BN_AQKV 40     // ni 40..79 : aQ|aK|aV
#define BN_O    80     // ni 80..103: Wout
#define BN_AO   104    // ni 104..127: Waout
#define BIMG_TOT  ((size_t)128 * KT96 * BTILE)
__device__ uint2 g_bimg[BIMG_TOT];

// ---------------- helpers ----------------
__device__ __forceinline__ unsigned pk(float a, float b) {
    unsigned r;
    asm("cvt.rn.bf16x2.f32 %0, %1, %2;" : "=r"(r) : "f"(b), "f"(a));
    return r;
}
__device__ __forceinline__ uint2 packsplit(float a, float b) {
    uint2 r;
    r.x = pk(a, b);
    float ha = __uint_as_float(r.x << 16);
    float hb = __uint_as_float(r.x & 0xffff0000u);
    r.y = pk(a - ha, b - hb);
    return r;
}
__device__ __forceinline__ void mma16(float* c, const unsigned* a, const unsigned* b) {
    asm volatile(
        "mma.sync.aligned.m16n8k16.row.col.f32.bf16.bf16.f32 "
        "{%0,%1,%2,%3},{%4,%5,%6,%7},{%8,%9},{%0,%1,%2,%3};"
        : "+f"(c[0]), "+f"(c[1]), "+f"(c[2]), "+f"(c[3])
        : "r"(a[0]), "r"(a[1]), "r"(a[2]), "r"(a[3]), "r"(b[0]), "r"(b[1]));
}
__device__ __forceinline__ void mma3b(float* c, const unsigned* ah, const unsigned* al,
                                      const unsigned* bh, const unsigned* bl) {
    mma16(c, al, bh);
    mma16(c, ah, bl);
    mma16(c, ah, bh);
}
__device__ __forceinline__ void cpasync16(unsigned dst, const void* src) {
    asm volatile("cp.async.cg.shared.global [%0], [%1], 16;" :: "r"(dst), "l"(src));
}

// ---------------- fused operand pack kernels ----------------
// all 8 weight tensors -> g_bimg. grid (128 ntiles, 96 kt)
__global__ __launch_bounds__(256) void pack_w(
    const float* __restrict__ Wq,  const float* __restrict__ Wk,  const float* __restrict__ Wv,
    const float* __restrict__ aWq, const float* __restrict__ aWk, const float* __restrict__ aWv,
    const float* __restrict__ Wo,  const float* __restrict__ aWo)
{
    int x = blockIdx.x, kt = blockIdx.y;
    const float* src; int N, ni;
    if      (x < 24)  { src = Wq;  N = 3072; ni = x; }
    else if (x < 32)  { src = Wk;  N = 1024; ni = x - 24; }
    else if (x < 40)  { src = Wv;  N = 1024; ni = x - 32; }
    else if (x < 64)  { src = aWq; N = 3072; ni = x - 40; }
    else if (x < 72)  { src = aWk; N = 1024; ni = x - 64; }
    else if (x < 80)  { src = aWv; N = 1024; ni = x - 72; }
    else if (x < 104) { src = Wo;  N = 3072; ni = x - 80; }
    else              { src = aWo; N = 3072; ni = x - 104; }

    int tid = threadIdx.x;
    int c = tid & 127, kg = tid >> 7;
    uint2* d = g_bimg + ((size_t)x * KT96 + kt) * BTILE;
    const float* s = src + (size_t)(kt * 32) * N + ni * 128 + c;
#pragma unroll
    for (int i = 0; i < 8; i++) {
        int kp = kg * 8 + i;
        float a = s[(size_t)(2 * kp) * N];
        float b = s[(size_t)(2 * kp + 1) * N];
        d[kp * 132 + c] = packsplit(a, b);
    }
}

// A image pack: mi<32 -> srcA rows mi*128, else srcB rows (mi-32)*128
__global__ __launch_bounds__(256) void pack_act(
    const float* __restrict__ srcA, const float* __restrict__ srcB, size_t abase)
{
    int mi = blockIdx.x, kt = blockIdx.y;
    const float* src = (mi < 32) ? srcA + (size_t)(mi * 128) * DMODEL
                                 : srcB + (size_t)((mi - 32) * 128) * DMODEL;
    int tid = threadIdx.x;
    int kp = tid & 15, r0 = tid >> 4;
    uint2* d = g_aimg + abase + ((size_t)mi * KT96 + kt) * ATILE;
    const float* s = src + kt * 32 + kp * 2;
#pragma unroll
    for (int i = 0; i < 8; i++) {
        int r = r0 + i * 16;
        float2 v = *(const float2*)(s + (size_t)r * DMODEL);
        d[r * 20 + kp] = packsplit(v.x, v.y);
    }
}

// ---------------- GEMM core (R9, proven) ----------------
#define GST 4672   // uint2 per stage (2560 A + 2112 B)

__device__ __forceinline__ void gcopy(unsigned sb, int stage,
                                      const uint2* __restrict__ Aimg,
                                      const uint2* __restrict__ Bimg,
                                      int atile, int btile, int tid)
{
    unsigned abase = sb + stage * (GST * 8);
    const uint2* as = Aimg + (size_t)atile * ATILE;
#pragma unroll
    for (int i = 0; i < 5; i++) {
        int c = tid + i * 256;
        cpasync16(abase + c * 16, as + c * 2);
    }
    unsigned bbase = abase + ATILE * 8;
    const uint2* bs = Bimg + (size_t)btile * BTILE;
#pragma unroll
    for (int i = 0; i < 5; i++) {
        int c = tid + i * 256;
        if (c < 1056) cpasync16(bbase + c * 16, bs + c * 2);
    }
    asm volatile("cp.async.commit_group;");
}

__device__ __forceinline__ void gcompute(const uint2* st, float acc[4][4][4],
                                         int wm, int wn, int g, int tg)
{
    const uint2 (*As)[20]  = (const uint2(*)[20])st;
    const uint2 (*Bs)[132] = (const uint2(*)[132])(st + ATILE);
#pragma unroll
    for (int kk = 0; kk < 2; kk++) {
        unsigned ah[4][4], al[4][4], bh[4][2], bl[4][2];
#pragma unroll
        for (int mt = 0; mt < 4; mt++) {
            int m0 = wm + mt * 16;
            uint2 q0 = As[m0 + g][kk * 8 + tg];
            uint2 q1 = As[m0 + g + 8][kk * 8 + tg];
            uint2 q2 = As[m0 + g][kk * 8 + tg + 4];
            uint2 q3 = As[m0 + g + 8][kk * 8 + tg + 4];
            ah[mt][0] = q0.x; ah[mt][1] = q1.x; ah[mt][2] = q2.x; ah[mt][3] = q3.x;
            al[mt][0] = q0.y; al[mt][1] = q1.y; al[mt][2] = q2.y; al[mt][3] = q3.y;
        }
#pragma unroll
        for (int nt = 0; nt < 4; nt++) {
            int n0 = wn + nt * 8;
            uint2 c0 = Bs[kk * 8 + tg][n0 + g];
            uint2 c1 = Bs[kk * 8 + tg + 4][n0 + g];
            bh[nt][0] = c0.x; bh[nt][1] = c1.x;
            bl[nt][0] = c0.y; bl[nt][1] = c1.y;
        }
#pragma unroll
        for (int mt = 0; mt < 4; mt++)
#pragma unroll
            for (int nt = 0; nt < 4; nt++)
                mma3b(acc[mt][nt], ah[mt], al[mt], bh[nt], bl[nt]);
    }
}

__device__ __forceinline__ void gemm_mainloop(
    unsigned sb, const uint2* gsm_g, const uint2* Aimg, const uint2* Bimg,
    int abase, int bbase, int tid, float acc[4][4][4], int wm, int wn, int g, int tg)
{
    gcopy(sb, 0, Aimg, Bimg, abase + 0, bbase + 0, tid);
    gcopy(sb, 1, Aimg, Bimg, abase + 1, bbase + 1, tid);
    for (int kt = 0; kt < KT96; kt++) {
        if (kt < KT96 - 1) asm volatile("cp.async.wait_group 1;");
        else               asm volatile("cp.async.wait_group 0;");
        __syncthreads();
        gcompute(gsm_g + (kt & 1) * GST, acc, wm, wn, g, tg);
        __syncthreads();
        if (kt + 2 < KT96)
            gcopy(sb, kt & 1, Aimg, Bimg, abase + kt + 2, bbase + kt + 2, tid);
    }
}

// ---------------- fused QKV (+enc) projection GEMM ----------------
// grid (40, 36): ni 0..23 Q | 24..31 K | 32..39 V ; mi 0..31 img | 32..35 txt
__global__ __launch_bounds__(256, 2) void gemm_qkv(
    const float* __restrict__ bq,  const float* __restrict__ bk,  const float* __restrict__ bv,
    const float* __restrict__ abq, const float* __restrict__ abk, const float* __restrict__ abv)
{
    extern __shared__ uint2 gsm[];
    unsigned sb = (unsigned)__cvta_generic_to_shared(gsm);

    const int tid  = threadIdx.x;
    const int mi   = blockIdx.y;
    const int ni   = blockIdx.x;
    const int warp = tid >> 5, lane = tid & 31;
    const int g    = lane >> 2, tg = lane & 3;
    const int wm   = (warp >> 2) * 64;
    const int wn   = (warp & 3) * 32;
    const bool txt = (mi >= 32);
    // enc tiles use aQ/aK/aV weights: B ntile offset 40
    const int bbase = (txt ? ni + 40 : ni) * KT96;
    const int abase = mi * KT96;

    float acc[4][4][4];
#pragma unroll
    for (int i = 0; i < 4; i++)
#pragma unroll
        for (int j = 0; j < 4; j++)
#pragma unroll
            for (int r = 0; r < 4; r++) acc[i][j][r] = 0.f;

    gemm_mainloop(sb, gsm, g_aimg + AIMG_QKV, g_bimg, abase, bbase, tid,
                  acc, wm, wn, g, tg);

    // epilogue: head-major scatter with joint-token mapping + per-stream bias
    float* dst;
    const float* bias;
    int nloc, hgrp;
    if (ni < 24)      { dst = g_q; bias = txt ? abq : bq; nloc = ni * 128;        hgrp = ni; }
    else if (ni < 32) { dst = g_k; bias = txt ? abk : bk; nloc = (ni - 24) * 128; hgrp = ni - 24; }
    else              { dst = g_v; bias = txt ? abv : bv; nloc = (ni - 32) * 128; hgrp = ni - 32; }

#pragma unroll
    for (int mt = 0; mt < 4; mt++) {
        int row = wm + mt * 16 + g;
        int tokA = (mi * 128 + row + STXT) % SALL;
        int tokB = (mi * 128 + row + 8 + STXT) % SALL;
#pragma unroll
        for (int nt = 0; nt < 4; nt++) {
            int nc = wn + nt * 8 + tg * 2;          // 0..127 within this head
            float b0 = bias[nloc + nc], b1 = bias[nloc + nc + 1];
            size_t iA = ((size_t)hgrp * SALL + tokA) * HD + nc;
            size_t iB = ((size_t)hgrp * SALL + tokB) * HD + nc;
            dst[iA]     = acc[mt][nt][0] + b0;
            dst[iA + 1] = acc[mt][nt][1] + b1;
            dst[iB]     = acc[mt][nt][2] + b0;
            dst[iB + 1] = acc[mt][nt][3] + b1;
        }
    }
}

// ---------------- fused output projection GEMM ----------------
// grid (24, 36): mi 0..31 -> Wout, img rows; mi 32..35 -> Waout, txt rows
__global__ __launch_bounds__(256, 2) void gemm_out(
    const float* __restrict__ bout, const float* __restrict__ baout, float* __restrict__ out)
{
    extern __shared__ uint2 gsm[];
    unsigned sb = (unsigned)__cvta_generic_to_shared(gsm);

    const int tid  = threadIdx.x;
    const int mi   = blockIdx.y;
    const int ni   = blockIdx.x;
    const int warp = tid >> 5, lane = tid & 31;
    const int g    = lane >> 2, tg = lane & 3;
    const int wm   = (warp >> 2) * 64;
    const int wn   = (warp & 3) * 32;
    const int bbase = ((mi < 32) ? BN_O + ni : BN_AO + ni) * KT96;
    const int abase = mi * KT96;

    float acc[4][4][4];
#pragma unroll
    for (int i = 0; i < 4; i++)
#pragma unroll
        for (int j = 0; j < 4; j++)
#pragma unroll
            for (int r = 0; r < 4; r++) acc[i][j][r] = 0.f;

    gemm_mainloop(sb, gsm, g_aimg + AIMG_AO, g_bimg, abase, bbase, tid,
                  acc, wm, wn, g, tg);

    const float* bias = (mi < 32) ? bout : baout;
    int rbase = (mi < 32) ? mi * 128 : SIMG + (mi - 32) * 128;
#pragma unroll
    for (int mt = 0; mt < 4; mt++) {
        int m = rbase + wm + mt * 16 + g;
#pragma unroll
        for (int nt = 0; nt < 4; nt++) {
            int n = ni * 128 + wn + nt * 8 + tg * 2;
            float b0 = bias[n], b1 = bias[n + 1];
            out[(size_t)m * DMODEL + n]           = acc[mt][nt][0] + b0;
            out[(size_t)m * DMODEL + n + 1]       = acc[mt][nt][1] + b1;
            out[(size_t)(m + 8) * DMODEL + n]     = acc[mt][nt][2] + b0;
            out[(size_t)(m + 8) * DMODEL + n + 1] = acc[mt][nt][3] + b1;
        }
    }
}

// ---------------- RMSNorm + RoPE + pack (R7, proven) ----------------
template <int QMODE>
__device__ __forceinline__ void norm_rope_body(
    int row, const float* __restrict__ x, const float* __restrict__ w,
    const float* __restrict__ aw, const float* __restrict__ rope)
{
    int token = row % SALL;
    int tid = threadIdx.x;

    float v = x[(size_t)row * HD + tid];
    float ss = v * v;
#pragma unroll
    for (int o = 16; o; o >>= 1) ss += __shfl_xor_sync(0xffffffffu, ss, o);
    __shared__ float red[4];
    if ((tid & 31) == 0) red[tid >> 5] = ss;
    __syncthreads();
    float tot = red[0] + red[1] + red[2] + red[3];
    float r = rsqrtf(tot * (1.0f / HD) + 1e-6f);
    float wt = (token < STXT) ? aw[tid] : w[tid];
    float xn = v * r * wt;

    float c = rope[(size_t)token * HD + tid];
    float s = rope[(size_t)(SALL + token) * HD + tid];
    float part = __shfl_xor_sync(0xffffffffu, xn, 1);
    float xr = (tid & 1) ? part : -part;
    float res = xn * c + xr * s;
    if (QMODE) res *= 0.08838834764831845f;   // 1/sqrt(128)

    float nb = __shfl_down_sync(0xffffffffu, res, 1);
    if ((tid & 1) == 0) {
        uint2 pkd = packsplit(res, nb);
        if (QMODE) {
            g_qp[(size_t)row * 64 + (tid >> 1)] = pkd;
        } else {
            int kvh = row / SALL;
            size_t idx = (((size_t)(kvh * NT64 + (token >> 6)) * 64) + (tid >> 1)) * 64
                         + (token & 63);
            g_kp[idx] = pkd;
        }
    }
}

__global__ __launch_bounds__(128) void norm_q(
    const float* __restrict__ x, const float* __restrict__ w,
    const float* __restrict__ aw, const float* __restrict__ rope)
{
    norm_rope_body<1>(blockIdx.x, x, w, aw, rope);
}

// fused: norm_k (blocks 0..NKVH*SALL) + pack_v (rest)
__global__ __launch_bounds__(128) void norm_kv(
    const float* __restrict__ x, const float* __restrict__ w,
    const float* __restrict__ aw, const float* __restrict__ rope)
{
    int b = blockIdx.x;
    if (b < NKVH * SALL) {
        norm_rope_body<0>(b, x, w, aw, rope);
    } else {
        b -= NKVH * SALL;
        int kp = b & 31;
        int tile = (b >> 5) % NT64;
        int kvh = b / (32 * NT64);
        int hd = threadIdx.x;
        const float* v0 = g_v + ((size_t)kvh * SALL + tile * 64 + 2 * kp) * HD + hd;
        float a = v0[0], c = v0[HD];
        g_vp[(((size_t)(kvh * NT64 + tile) * 32) + kp) * 128 + hd] = packsplit(a, c);
    }
}

// ---------------- 3xBF16 flash attention (R7/R9, proven) ----------------
#define OFF_K0 8704
#define OFF_K1 13056
#define OFF_V0 17408
#define OFF_V1 21632
#define FLASH_U2 25856

__device__ __forceinline__ void issue_kv(unsigned sbase, int koff, int voff,
                                         int kvh, int jt, int tid)
{
    const uint2* ksrc = g_kp + (size_t)(kvh * NT64 + jt) * 64 * 64;
    const uint2* vsrc = g_vp + (size_t)(kvh * NT64 + jt) * 32 * 128;
#pragma unroll
    for (int c = tid; c < 2048; c += 256) {
        int kr = c >> 5, kc = (c & 31) * 2;
        cpasync16(sbase + (unsigned)(koff + kr * 68 + kc) * 8, ksrc + kr * 64 + kc);
        int vr = c >> 6, vc = (c & 63) * 2;
        cpasync16(sbase + (unsigned)(voff + vr * 132 + vc) * 8, vsrc + vr * 128 + vc);
    }
    asm volatile("cp.async.commit_group;");
}

__global__ __launch_bounds__(256, 1) void flash_attn()
{
    extern __shared__ uint2 fsm[];
    unsigned sbase = (unsigned)__cvta_generic_to_shared(fsm);

    const int head = blockIdx.y;
    const int kvh  = head / (NH / NKVH);
    const int mb   = blockIdx.x * 128;
    const int tid  = threadIdx.x, lane = tid & 31;
    const int g    = lane >> 2, tg = lane & 3;
    const int m0   = (tid >> 5) * 16;

    {
        const uint2* Qg = g_qp + ((size_t)head * SALL + mb) * 64;
        int r = tid >> 1, b = (tid & 1) * 32;
#pragma unroll
        for (int i = 0; i < 16; i++) {
            uint4 v = *(const uint4*)(Qg + (size_t)r * 64 + b + 2 * i);
            *(uint4*)&fsm[r * 68 + b + 2 * i] = v;
        }
    }

    issue_kv(sbase, OFF_K0, OFF_V0, kvh, 0, tid);

    float o[16][4];
#pragma unroll
    for (int i = 0; i < 16; i++)
#pragma unroll
        for (int j = 0; j < 4; j++) o[i][j] = 0.f;
    float mprev0 = -INFINITY, mprev1 = -INFINITY, l0 = 0.f, l1 = 0.f;

    for (int jt = 0; jt < NT64; jt++) {
        int cur = jt & 1;
        if (jt + 1 < NT64) {
            issue_kv(sbase, cur ? OFF_K0 : OFF_K1, cur ? OFF_V0 : OFF_V1, kvh, jt + 1, tid);
            asm volatile("cp.async.wait_group 1;");
        } else {
            asm volatile("cp.async.wait_group 0;");
        }
        __syncthreads();

        const uint2* Kb = fsm + (cur ? OFF_K1 : OFF_K0);
        const uint2* Vb = fsm + (cur ? OFF_V1 : OFF_V0);

        float s[8][4];
#pragma unroll
        for (int nt = 0; nt < 8; nt++) { s[nt][0] = s[nt][1] = s[nt][2] = s[nt][3] = 0.f; }
#pragma unroll
        for (int kk = 0; kk < 8; kk++) {
            uint2 q0 = fsm[(m0 + g) * 68 + kk * 8 + tg];
            uint2 q1 = fsm[(m0 + g + 8) * 68 + kk * 8 + tg];
            uint2 q2 = fsm[(m0 + g) * 68 + kk * 8 + tg + 4];
            uint2 q3 = fsm[(m0 + g + 8) * 68 + kk * 8 + tg + 4];
            unsigned ah[4] = {q0.x, q1.x, q2.x, q3.x};
            unsigned al[4] = {q0.y, q1.y, q2.y, q3.y};
#pragma unroll
            for (int nt = 0; nt < 8; nt++) {
                uint2 k0 = Kb[(kk * 8 + tg) * 68 + nt * 8 + g];
                uint2 k1 = Kb[(kk * 8 + tg + 4) * 68 + nt * 8 + g];
                unsigned bh[2] = {k0.x, k1.x};
                unsigned bl[2] = {k0.y, k1.y};
                mma3b(s[nt], ah, al, bh, bl);
            }
        }

        float mx0 = -INFINITY, mx1 = -INFINITY;
#pragma unroll
        for (int nt = 0; nt < 8; nt++) {
            mx0 = fmaxf(mx0, fmaxf(s[nt][0], s[nt][1]));
            mx1 = fmaxf(mx1, fmaxf(s[nt][2], s[nt][3]));
        }
        mx0 = fmaxf(mx0, __shfl_xor_sync(0xffffffffu, mx0, 1));
        mx0 = fmaxf(mx0, __shfl_xor_sync(0xffffffffu, mx0, 2));
        mx1 = fmaxf(mx1, __shfl_xor_sync(0xffffffffu, mx1, 1));
        mx1 = fmaxf(mx1, __shfl_xor_sync(0xffffffffu, mx1, 2));

        float mn0 = fmaxf(mprev0, mx0), mn1 = fmaxf(mprev1, mx1);
        float al0 = __expf(mprev0 - mn0), al1 = __expf(mprev1 - mn1);
        float sum0 = 0.f, sum1 = 0.f;
#pragma unroll
        for (int nt = 0; nt < 8; nt++) {
            s[nt][0] = __expf(s[nt][0] - mn0);
            s[nt][1] = __expf(s[nt][1] - mn0);
            s[nt][2] = __expf(s[nt][2] - mn1);
            s[nt][3] = __expf(s[nt][3] - mn1);
            sum0 += s[nt][0] + s[nt][1];
            sum1 += s[nt][2] + s[nt][3];
        }
        sum0 += __shfl_xor_sync(0xffffffffu, sum0, 1);
        sum0 += __shfl_xor_sync(0xffffffffu, sum0, 2);
        sum1 += __shfl_xor_sync(0xffffffffu, sum1, 1);
        sum1 += __shfl_xor_sync(0xffffffffu, sum1, 2);
        l0 = l0 * al0 + sum0;
        l1 = l1 * al1 + sum1;
        mprev0 = mn0; mprev1 = mn1;
        if (__any_sync(0xffffffffu, (al0 < 1.f) | (al1 < 1.f))) {
#pragma unroll
            for (int nt = 0; nt < 16; nt++) {
                o[nt][0] *= al0; o[nt][1] *= al0;
                o[nt][2] *= al1; o[nt][3] *= al1;
            }
        }

#pragma unroll
        for (int kk = 0; kk < 4; kk++) {
            uint2 u0 = packsplit(s[2 * kk][0],     s[2 * kk][1]);
            uint2 u1 = packsplit(s[2 * kk][2],     s[2 * kk][3]);
            uint2 u2 = packsplit(s[2 * kk + 1][0], s[2 * kk + 1][1]);
            uint2 u3 = packsplit(s[2 * kk + 1][2], s[2 * kk + 1][3]);
            unsigned ah[4] = {u0.x, u1.x, u2.x, u3.x};
            unsigned al2[4] = {u0.y, u1.y, u2.y, u3.y};
#pragma unroll
            for (int nt = 0; nt < 16; nt++) {
                uint2 v0 = Vb[(kk * 8 + tg) * 132 + nt * 8 + g];
                uint2 v1 = Vb[(kk * 8 + tg + 4) * 132 + nt * 8 + g];
                unsigned bh[2] = {v0.x, v1.x};
                unsigned bl[2] = {v0.y, v1.y};
                mma3b(o[nt], ah, al2, bh, bl);
            }
        }
        __syncthreads();
    }

    float r0 = 1.f / l0, r1 = 1.f / l1;
    int tok0 = mb + m0 + g;
#pragma unroll
    for (int nt = 0; nt < 16; nt++) {
        int col = head * HD + nt * 8 + 2 * tg;
        float2 v0 = make_float2(o[nt][0] * r0, o[nt][1] * r0);
        float2 v1 = make_float2(o[nt][2] * r1, o[nt][3] * r1);
        *(float2*)&g_ao[(size_t)tok0 * DMODEL + col]       = v0;
        *(float2*)&g_ao[(size_t)(tok0 + 8) * DMODEL + col] = v1;
    }
}

// ---------------- launch ----------------
#define GEMM_SMEM  (2 * GST * 8)           // 74752
#define FLASH_SMEM (FLASH_U2 * 8)          // 206848

extern "C" void kernel_launch(void* const* d_in, const int* in_sizes, int n_in,
                              void* d_out, int out_size)
{
    const float* hs    = (const float*)d_in[0];
    const float* enc   = (const float*)d_in[1];
    const float* rope  = (const float*)d_in[2];
    const float* Wq    = (const float*)d_in[3];
    const float* bq    = (const float*)d_in[4];
    const float* Wk    = (const float*)d_in[5];
    const float* bk    = (const float*)d_in[6];
    const float* Wv    = (const float*)d_in[7];
    const float* bv    = (const float*)d_in[8];
    const float* aWq   = (const float*)d_in[9];
    const float* abq   = (const float*)d_in[10];
    const float* aWk   = (const float*)d_in[11];
    const float* abk   = (const float*)d_in[12];
    const float* aWv   = (const float*)d_in[13];
    const float* abv   = (const float*)d_in[14];
    const float* nq    = (const float*)d_in[15];
    const float* nk    = (const float*)d_in[16];
    const float* anq   = (const float*)d_in[17];
    const float* ank   = (const float*)d_in[18];
    const float* Wout  = (const float*)d_in[19];
    const float* bout  = (const float*)d_in[20];
    const float* Waout = (const float*)d_in[21];
    const float* baout = (const float*)d_in[22];
    float* out = (float*)d_out;

    float *pq, *pk_, *pao;
    cudaGetSymbolAddress((void**)&pq,  g_q);
    cudaGetSymbolAddress((void**)&pk_, g_k);
    cudaGetSymbolAddress((void**)&pao, g_ao);

    cudaFuncSetAttribute(gemm_qkv,  cudaFuncAttributeMaxDynamicSharedMemorySize, GEMM_SMEM);
    cudaFuncSetAttribute(gemm_out,  cudaFuncAttributeMaxDynamicSharedMemorySize, GEMM_SMEM);
    cudaFuncSetAttribute(flash_attn, cudaFuncAttributeMaxDynamicSharedMemorySize, FLASH_SMEM);

    // NOTE: launch order positions flash_attn as launch #6 for ncu (-s 5 -c 1)
    // 1: all weight packs
    pack_w<<<dim3(128, KT96), 256>>>(Wq, Wk, Wv, aWq, aWk, aWv, Wout, Waout);
    // 2: hs + enc activation pack (A image for QKV gemm)
    pack_act<<<dim3(36, KT96), 256>>>(hs, enc, AIMG_QKV);
    // 3: all six projections in one launch (per-stream biases!)
    gemm_qkv<<<dim3(40, 36), 256, GEMM_SMEM>>>(bq, bk, bv, abq, abk, abv);
    // 4: q norm/rope/pack
    norm_q<<<NH * SALL, 128>>>(pq, nq, anq, rope);
    // 5: k norm/rope/pack + v pack
    norm_kv<<<NKVH * SALL + NKVH * NT64 * 32, 128>>>(pk_, nk, ank, rope);
    // 6: flash attention  (profiled launch)
    flash_attn<<<dim3(SALL / 128, NH), 256, FLASH_SMEM>>>();
    // 7: attention-output pack (img rows at offset STXT, txt rows at 0)
    pack_act<<<dim3(36, KT96), 256>>>(pao + (size_t)STXT * DMODEL, pao, AIMG_AO);
    // 8: both output projections in one launch
    gemm_out<<<dim3(24, 36), 256, GEMM_SMEM>>>(bout, baout, out);
}